// round 10
// baseline (speedup 1.0000x reference)
#include <cuda_runtime.h>
#include <cuda_fp16.h>
#include <cstdint>

// ----------------------------------------------------------------------------
// MultiHeadAttn via fp16 2-term split + mma.sync:
//   A side exact: A' = [A_hi | A_lo] fp16 (K'=1024); B side hi-only, scaled 2^13.
//   1) convert_x : x[8192,512] -> A1 fp16 [8192,1024]  (hi|lo)
//   2) repack_b  : Wq,Wv -> B1 fp16 [1024,512]; Wup -> B2 [512,512]  (x 2^13)
//   3) gemm_mma  : QV[8192,1024] fp32 = A1 @ B1dup^T, escale=2^-13
//   4) band_attn : lane-per-row single-pass (no shfl); fp16 scores, f32x2 accum
//   5) gemm_mma  : out[8192,512] = A2 @ B2dup^T, escale=2^-21
// ----------------------------------------------------------------------------

#define M_ROWS   8192
#define N_SEQ    4096
#define NHEAD    8
#define CONTEXT  10
#define KBIG     1024
#define NCHUNK   16          // 1024 / 64

#define BSCALE   8192.0f     // 2^13
#define CSCALE   256.0f      // 2^8
#define QSCALE   4096.0f     // 2^12: keeps fp16 score products in normal range

__device__ __half g_A1[M_ROWS * KBIG];
__device__ __half g_A2[M_ROWS * KBIG];
__device__ __half g_B1[1024 * 512];
__device__ __half g_B2[512  * 512];
__device__ float  g_QV[M_ROWS * 1024];

// ============================ PTX helpers ====================================
typedef unsigned long long u64;

__device__ __forceinline__ uint32_t smem_u32(const void* p) {
    uint32_t a;
    asm("{ .reg .u64 t; cvta.to.shared.u64 t, %1; cvt.u32.u64 %0, t; }"
        : "=r"(a) : "l"(p));
    return a;
}
__device__ __forceinline__ void cp_async16(uint32_t dst, const void* src) {
    asm volatile("cp.async.cg.shared.global [%0], [%1], 16;"
                 :: "r"(dst), "l"(src) : "memory");
}
__device__ __forceinline__ void cp_commit() {
    asm volatile("cp.async.commit_group;" ::: "memory");
}
template <int N>
__device__ __forceinline__ void cp_wait() {
    asm volatile("cp.async.wait_group %0;" :: "n"(N) : "memory");
}
__device__ __forceinline__ void ldm_x4(uint32_t& r0, uint32_t& r1,
                                       uint32_t& r2, uint32_t& r3, uint32_t a) {
    asm volatile("ldmatrix.sync.aligned.m8n8.x4.shared.b16 {%0,%1,%2,%3}, [%4];"
                 : "=r"(r0), "=r"(r1), "=r"(r2), "=r"(r3) : "r"(a));
}
__device__ __forceinline__ void mma16816(float* c, const uint32_t* a,
                                         const uint32_t* b) {
    asm volatile(
        "mma.sync.aligned.m16n8k16.row.col.f32.f16.f16.f32 "
        "{%0,%1,%2,%3}, {%4,%5,%6,%7}, {%8,%9}, {%0,%1,%2,%3};"
        : "+f"(c[0]), "+f"(c[1]), "+f"(c[2]), "+f"(c[3])
        : "r"(a[0]), "r"(a[1]), "r"(a[2]), "r"(a[3]), "r"(b[0]), "r"(b[1]));
}
__device__ __forceinline__ __half2 u2h(uint32_t v) {
    return *reinterpret_cast<__half2*>(&v);
}
__device__ __forceinline__ uint32_t h2u(__half2 v) {
    return *reinterpret_cast<uint32_t*>(&v);
}
__device__ __forceinline__ u64 pack2(float lo, float hi) {
    u64 r;
    asm("mov.b64 %0, {%1, %2};" : "=l"(r) : "f"(lo), "f"(hi));
    return r;
}
__device__ __forceinline__ void unpack2(u64 v, float &lo, float &hi) {
    asm("mov.b64 {%0, %1}, %2;" : "=f"(lo), "=f"(hi) : "l"(v));
}
__device__ __forceinline__ void ffma2(u64 &d, u64 a, u64 b) {
    asm("fma.rn.f32x2 %0, %1, %2, %0;" : "+l"(d) : "l"(a), "l"(b));
}
__device__ __forceinline__ void mul2(u64 &d, u64 a, u64 b) {
    asm("mul.rn.f32x2 %0, %1, %2;" : "=l"(d) : "l"(a), "l"(b));
}

// ======================= conversion / repack kernels =========================
__global__ void convert_x(const float* __restrict__ x,
                          __half* __restrict__ A1) {
    int idx = blockIdx.x * 256 + threadIdx.x;       // [0, 8192*128)
    int row = idx >> 7;
    int kq  = (idx & 127) * 4;
    float4 v = *(const float4*)(x + (size_t)row * 512 + kq);
    __half h0 = __float2half_rn(v.x), h1 = __float2half_rn(v.y);
    __half h2 = __float2half_rn(v.z), h3 = __float2half_rn(v.w);
    __half l0 = __float2half_rn(v.x - __half2float(h0));
    __half l1 = __float2half_rn(v.y - __half2float(h1));
    __half l2 = __float2half_rn(v.z - __half2float(h2));
    __half l3 = __float2half_rn(v.w - __half2float(h3));
    __half* p = A1 + (size_t)row * KBIG;
    __half2 hv[2] = {__halves2half2(h0, h1), __halves2half2(h2, h3)};
    __half2 lv[2] = {__halves2half2(l0, l1), __halves2half2(l2, l3)};
    *(uint2*)&p[kq]       = *(uint2*)hv;
    *(uint2*)&p[512 + kq] = *(uint2*)lv;
}

__global__ void repack_b(const float* __restrict__ Wq,
                         const float* __restrict__ Wv,
                         const float* __restrict__ Wup,
                         __half* __restrict__ B1,
                         __half* __restrict__ B2) {
    int idx = blockIdx.x * 256 + threadIdx.x;       // [0, 1024*512 + 512*512)
    if (idx < 1024 * 512) {
        int n = idx >> 9, d = idx & 511;
        float w;
        if (n < 512) {
            int hh = n >> 6, k2 = n & 63;
            w = Wq[hh * (512 * 64) + d * 64 + k2];
        } else {
            int nn = n - 512, hh = nn >> 6, k2 = nn & 63;
            w = Wv[hh * (512 * 64) + d * 64 + k2];
        }
        B1[n * 512 + d] = __float2half_rn(w * BSCALE);
    } else {
        int i2 = idx - 1024 * 512;
        int n = i2 >> 9, d = i2 & 511;
        B2[n * 512 + d] = __float2half_rn(Wup[d * 512 + n] * BSCALE);
    }
}

// ====================== HMMA fp16 GEMM =======================================
__device__ __forceinline__ void load_tiles(uint32_t sA, uint32_t sB,
                                           const __half* __restrict__ A,
                                           const __half* __restrict__ B,
                                           int bm, int bn, int ck, int tid) {
    const __half* Ab = A + (size_t)bm * KBIG + ck * 64;
    const __half* Bb = B + (size_t)bn * 512 + (ck & 7) * 64;  // B dup: hi twice
    #pragma unroll
    for (int g = 0; g < 8; g++) {
        int id  = g * 128 + tid;
        int row = id >> 3;
        int c16 = id & 7;
        uint32_t sw = row * 128 + ((c16 * 16) ^ ((row & 7) * 16));
        cp_async16(sA + sw, Ab + (size_t)row * KBIG + c16 * 8);
        cp_async16(sB + sw, Bb + (size_t)row * 512 + c16 * 8);
    }
}

__global__ __launch_bounds__(128)
void gemm_mma(const __half* __restrict__ A,
              const __half* __restrict__ B,
              float* __restrict__ C, int N, float escale) {
    extern __shared__ char smem[];
    uint32_t sb = smem_u32(smem);
    uint32_t SA[3] = {sb, sb + 32768, sb + 65536};
    uint32_t SB[3] = {sb + 16384, sb + 49152, sb + 81920};

    const int tid  = threadIdx.x;
    const int lane = tid & 31;
    const int warp = tid >> 5;
    const int wm   = (warp >> 1) * 64;
    const int wn   = (warp & 1) * 64;
    const int bm   = blockIdx.y * 128, bn = blockIdx.x * 128;

    const int fr = (lane & 7) + ((lane >> 3) & 1) * 8;
    const int fk = (lane >> 4) * 16;

    float acc[4][8][4];
    #pragma unroll
    for (int i = 0; i < 4; i++)
        #pragma unroll
        for (int j = 0; j < 8; j++)
            #pragma unroll
            for (int q = 0; q < 4; q++) acc[i][j][q] = 0.f;

    load_tiles(SA[0], SB[0], A, B, bm, bn, 0, tid); cp_commit();
    load_tiles(SA[1], SB[1], A, B, bm, bn, 1, tid); cp_commit();

    #pragma unroll 1
    for (int c = 0; c < NCHUNK; c++) {
        const int s = c % 3;
        uint32_t sA = SA[s], sBt = SB[s];

        if (c == NCHUNK - 1) cp_wait<0>(); else cp_wait<1>();
        __syncthreads();

        if (c + 2 < NCHUNK) {
            const int s2 = (c + 2) % 3;
            load_tiles(SA[s2], SB[s2], A, B, bm, bn, c + 2, tid);
            cp_commit();
        }

        #pragma unroll
        for (int ks = 0; ks < 4; ks++) {
            const int k0b = ks * 32;
            uint32_t af[4][4], bf[8][2];
            #pragma unroll
            for (int mi = 0; mi < 4; mi++) {
                int r = wm + mi * 16 + fr;
                uint32_t addr = sA + r * 128 + ((k0b + fk) ^ ((r & 7) * 16));
                ldm_x4(af[mi][0], af[mi][1], af[mi][2], af[mi][3], addr);
            }
            #pragma unroll
            for (int ni = 0; ni < 4; ni++) {
                int r = wn + ni * 16 + fr;
                uint32_t addr = sBt + r * 128 + ((k0b + fk) ^ ((r & 7) * 16));
                uint32_t r0, r1, r2, r3;
                ldm_x4(r0, r1, r2, r3, addr);
                bf[2 * ni][0]     = r0; bf[2 * ni][1]     = r2;
                bf[2 * ni + 1][0] = r1; bf[2 * ni + 1][1] = r3;
            }
            #pragma unroll
            for (int mi = 0; mi < 4; mi++)
                #pragma unroll
                for (int nj = 0; nj < 8; nj++)
                    mma16816(acc[mi][nj], af[mi], bf[nj]);
        }
    }

    const int er = lane >> 2;
    const int ec = (lane & 3) * 2;
    #pragma unroll
    for (int mi = 0; mi < 4; mi++) {
        #pragma unroll
        for (int nj = 0; nj < 8; nj++) {
            int row = bm + wm + mi * 16 + er;
            int col = bn + wn + nj * 8 + ec;
            *(float2*)(C + (size_t)row * N + col) =
                make_float2(acc[mi][nj][0] * escale, acc[mi][nj][1] * escale);
            *(float2*)(C + (size_t)(row + 8) * N + col) =
                make_float2(acc[mi][nj][2] * escale, acc[mi][nj][3] * escale);
        }
    }
}

// ============================ band attention =================================
// Lane-per-row, single-pass. Warp = 32 query rows, block = 64 rows (2 warps).
// Scores tiny (~1e-6) -> exp never overflows -> no max-subtraction, no shfl.
// Phase A: fp16 Vs tiles (pitch 72 halves = 36 banks, conflict-free uint4).
// Phase C: fp32 Vsf tiles (pitch 68 floats) with packed fma.rn.f32x2.
#define TILE3   64
#define VR3     (TILE3 + 2 * CONTEXT)   // 84
#define PH      72
#define PF      68

__global__ __launch_bounds__(64)
void band_attn_kernel(const float* __restrict__ QV,
                      __half* __restrict__ A2) {
    __shared__ float  Vsf[VR3 * PF];    // 22848 B
    __shared__ __half Vs [VR3 * PH];    // 12096 B
    __shared__ __half Qs [TILE3 * PH];  //  9216 B

    const int bx   = blockIdx.x;         // [0, 1024)
    const int tile = bx & 63;
    const int hd   = (bx >> 6) & 7;
    const int b    = bx >> 9;
    const int i0   = tile * TILE3;
    const int tid  = threadIdx.x;
    const int lane = tid & 31;
    const int warp = tid >> 5;

    // fill V band rows (fp32 + fp16 copies; zero-fill halo)
    for (int idx = tid; idx < VR3 * 16; idx += 64) {
        int r  = idx >> 4;
        int kq = idx & 15;
        int j  = i0 - CONTEXT + r;
        float4 v = make_float4(0.f, 0.f, 0.f, 0.f);
        if (j >= 0 && j < N_SEQ)
            v = *(const float4*)(QV + (size_t)(b * N_SEQ + j) * 1024 + 512 + hd * 64 + kq * 4);
        *(float4*)&Vsf[r * PF + kq * 4] = v;
        __half2 p0 = __floats2half2_rn(v.x, v.y);
        __half2 p1 = __floats2half2_rn(v.z, v.w);
        *(uint2*)&Vs[r * PH + kq * 4] = make_uint2(h2u(p0), h2u(p1));
    }
    // fill Q rows scaled by 2^12 (fp16)
    for (int idx = tid; idx < TILE3 * 16; idx += 64) {
        int r  = idx >> 4;
        int kq = idx & 15;
        float4 v = *(const float4*)(QV + (size_t)(b * N_SEQ + i0 + r) * 1024 + hd * 64 + kq * 4);
        __half2 p0 = __floats2half2_rn(v.x * QSCALE, v.y * QSCALE);
        __half2 p1 = __floats2half2_rn(v.z * QSCALE, v.w * QSCALE);
        *(uint2*)&Qs[r * PH + kq * 4] = make_uint2(h2u(p0), h2u(p1));
    }
    __syncthreads();

    const int iq = warp * 32 + lane;     // this lane's query row (local)
    const int i  = i0 + iq;              // global row in sequence

    // own Q row -> registers (conflict-free: 36-bank row stride)
    uint4 qr[8];
    const uint4* qp = (const uint4*)&Qs[iq * PH];
    #pragma unroll
    for (int k = 0; k < 8; k++) qr[k] = qp[k];

    u64 c[32];                           // 64-dim fp32 accumulator (f32x2)
    #pragma unroll
    for (int k = 0; k < 32; k++) c[k] = 0ull;
    float esum = 0.f;

    const float sscale = 1.0f / (16.0f * QSCALE);

    #pragma unroll 1
    for (int d = 0; d <= 2 * CONTEXT; d++) {
        if (d == CONTEXT) continue;      // diagonal excluded

        // score s_d = Q_i . V_{i+d-10} (fp16, 4 parallel accumulators)
        const uint4* vp = (const uint4*)&Vs[(iq + d) * PH];
        __half2 a0 = __float2half2_rn(0.f), a1 = a0, a2 = a0, a3 = a0;
        #pragma unroll
        for (int k = 0; k < 8; k++) {
            uint4 vv = vp[k];
            a0 = __hfma2(u2h(qr[k].x), u2h(vv.x), a0);
            a1 = __hfma2(u2h(qr[k].y), u2h(vv.y), a1);
            a2 = __hfma2(u2h(qr[k].z), u2h(vv.z), a2);
            a3 = __hfma2(u2h(qr[k].w), u2h(vv.w), a3);
        }
        __half2 at = __hadd2(__hadd2(a0, a1), __hadd2(a2, a3));
        float s = (__low2float(at) + __high2float(at)) * sscale;

        int j = i + d - CONTEXT;
        float e = (j >= 0 && j < N_SEQ) ? __expf(s) : 0.f;
        esum += e;

        // C += e * V (fp32 smem, packed f32x2)
        u64 e2 = pack2(e, e);
        const float* vf = &Vsf[(iq + d) * PF];
        #pragma unroll
        for (int k = 0; k < 16; k++) {
            float4 vv = *(const float4*)(vf + k * 4);
            ffma2(c[2 * k],     e2, pack2(vv.x, vv.y));
            ffma2(c[2 * k + 1], e2, pack2(vv.z, vv.w));
        }
    }

    // normalize + scaled hi/lo split store
    float inv = __fdividef(CSCALE, esum);
    u64 inv2 = pack2(inv, inv);
    __half* cp = A2 + (size_t)(b * N_SEQ + i) * KBIG + hd * 64;
    #pragma unroll
    for (int g = 0; g < 8; g++) {
        uint32_t hi[4], lo[4];
        #pragma unroll
        for (int t = 0; t < 4; t++) {
            u64 m;
            mul2(m, c[4 * g + t], inv2);
            float f0, f1;
            unpack2(m, f0, f1);
            __half2 h = __floats2half2_rn(f0, f1);
            float2 hf = __half22float2(h);
            __half2 l = __floats2half2_rn(f0 - hf.x, f1 - hf.y);
            hi[t] = h2u(h);
            lo[t] = h2u(l);
        }
        *(uint4*)(cp + g * 8)       = make_uint4(hi[0], hi[1], hi[2], hi[3]);
        *(uint4*)(cp + 512 + g * 8) = make_uint4(lo[0], lo[1], lo[2], lo[3]);
    }
}

// ================================ launch =====================================
extern "C" void kernel_launch(void* const* d_in, const int* in_sizes, int n_in,
                              void* d_out, int out_size) {
    const float* x   = (const float*)d_in[0];
    const float* Wq  = (const float*)d_in[1];
    const float* Wv  = (const float*)d_in[2];
    const float* Wup = (const float*)d_in[3];
    float* out = (float*)d_out;

    __half *a1, *a2, *b1, *b2;
    float *qv;
    cudaGetSymbolAddress((void**)&a1, g_A1);
    cudaGetSymbolAddress((void**)&a2, g_A2);
    cudaGetSymbolAddress((void**)&b1, g_B1);
    cudaGetSymbolAddress((void**)&b2, g_B2);
    cudaGetSymbolAddress((void**)&qv, g_QV);

    const int SMEM_BYTES = 98304;   // 3 stages x 32KB (gemm)
    cudaFuncSetAttribute(gemm_mma, cudaFuncAttributeMaxDynamicSharedMemorySize,
                         SMEM_BYTES);

    convert_x<<<(M_ROWS * 128) / 256, 256>>>(x, a1);
    repack_b<<<(1024 * 512 + 512 * 512) / 256, 256>>>(Wq, Wv, Wup, b1, b2);

    gemm_mma<<<dim3(1024 / 128, M_ROWS / 128), 128, SMEM_BYTES>>>(
        a1, b1, qv, 1024, 1.0f / BSCALE);
    band_attn_kernel<<<2 * NHEAD * (N_SEQ / TILE3), 64>>>(qv, a2);
    gemm_mma<<<dim3(512 / 128, M_ROWS / 128), 128, SMEM_BYTES>>>(
        a2, b2, out, 512, 1.0f / (BSCALE * CSCALE));
}

// round 11
// speedup vs baseline: 1.6345x; 1.6345x over previous
#include <cuda_runtime.h>
#include <cuda_fp16.h>
#include <cstdint>

// ----------------------------------------------------------------------------
// MultiHeadAttn via fp16 2-term split + mma.sync:
//   1) convert_x : x[8192,512] -> A1 fp16 [8192,1024]  (hi|lo)
//   2) repack_b  : Wq,Wv -> B1 fp16 [1024,512]; Wup -> B2 [512,512]  (x 2^13)
//   3) gemm_mma  : QV[8192,1024] fp32 = A1 @ B1dup^T, escale=2^-13
//   4) band_attn : tensor-core tiles: S=Q@V^T (mma) -> mask+exp -> P (fp16)
//                  -> O=P@V (mma, K=96) -> normalize -> hi/lo split store
//   5) gemm_mma  : out[8192,512] = A2 @ B2dup^T, escale=2^-21
// ----------------------------------------------------------------------------

#define M_ROWS   8192
#define N_SEQ    4096
#define NHEAD    8
#define CONTEXT  10
#define KBIG     1024
#define NCHUNK   16          // 1024 / 64

#define BSCALE   8192.0f     // 2^13
#define CSCALE   256.0f      // 2^8
#define QSCALE   4096.0f     // 2^12

__device__ __half g_A1[M_ROWS * KBIG];
__device__ __half g_A2[M_ROWS * KBIG];
__device__ __half g_B1[1024 * 512];
__device__ __half g_B2[512  * 512];
__device__ float  g_QV[M_ROWS * 1024];

// ============================ PTX helpers ====================================
__device__ __forceinline__ uint32_t smem_u32(const void* p) {
    uint32_t a;
    asm("{ .reg .u64 t; cvta.to.shared.u64 t, %1; cvt.u32.u64 %0, t; }"
        : "=r"(a) : "l"(p));
    return a;
}
__device__ __forceinline__ void cp_async16(uint32_t dst, const void* src) {
    asm volatile("cp.async.cg.shared.global [%0], [%1], 16;"
                 :: "r"(dst), "l"(src) : "memory");
}
__device__ __forceinline__ void cp_commit() {
    asm volatile("cp.async.commit_group;" ::: "memory");
}
template <int N>
__device__ __forceinline__ void cp_wait() {
    asm volatile("cp.async.wait_group %0;" :: "n"(N) : "memory");
}
__device__ __forceinline__ void ldm_x4(uint32_t& r0, uint32_t& r1,
                                       uint32_t& r2, uint32_t& r3, uint32_t a) {
    asm volatile("ldmatrix.sync.aligned.m8n8.x4.shared.b16 {%0,%1,%2,%3}, [%4];"
                 : "=r"(r0), "=r"(r1), "=r"(r2), "=r"(r3) : "r"(a));
}
__device__ __forceinline__ void mma16816(float* c, const uint32_t* a,
                                         const uint32_t* b) {
    asm volatile(
        "mma.sync.aligned.m16n8k16.row.col.f32.f16.f16.f32 "
        "{%0,%1,%2,%3}, {%4,%5,%6,%7}, {%8,%9}, {%0,%1,%2,%3};"
        : "+f"(c[0]), "+f"(c[1]), "+f"(c[2]), "+f"(c[3])
        : "r"(a[0]), "r"(a[1]), "r"(a[2]), "r"(a[3]), "r"(b[0]), "r"(b[1]));
}
__device__ __forceinline__ __half2 u2h(uint32_t v) {
    return *reinterpret_cast<__half2*>(&v);
}
__device__ __forceinline__ uint32_t h2u(__half2 v) {
    return *reinterpret_cast<uint32_t*>(&v);
}

// ======================= conversion / repack kernels =========================
__global__ void convert_x(const float* __restrict__ x,
                          __half* __restrict__ A1) {
    int idx = blockIdx.x * 256 + threadIdx.x;       // [0, 8192*128)
    int row = idx >> 7;
    int kq  = (idx & 127) * 4;
    float4 v = *(const float4*)(x + (size_t)row * 512 + kq);
    __half h0 = __float2half_rn(v.x), h1 = __float2half_rn(v.y);
    __half h2 = __float2half_rn(v.z), h3 = __float2half_rn(v.w);
    __half l0 = __float2half_rn(v.x - __half2float(h0));
    __half l1 = __float2half_rn(v.y - __half2float(h1));
    __half l2 = __float2half_rn(v.z - __half2float(h2));
    __half l3 = __float2half_rn(v.w - __half2float(h3));
    __half* p = A1 + (size_t)row * KBIG;
    __half2 hv[2] = {__halves2half2(h0, h1), __halves2half2(h2, h3)};
    __half2 lv[2] = {__halves2half2(l0, l1), __halves2half2(l2, l3)};
    *(uint2*)&p[kq]       = *(uint2*)hv;
    *(uint2*)&p[512 + kq] = *(uint2*)lv;
}

__global__ void repack_b(const float* __restrict__ Wq,
                         const float* __restrict__ Wv,
                         const float* __restrict__ Wup,
                         __half* __restrict__ B1,
                         __half* __restrict__ B2) {
    int idx = blockIdx.x * 256 + threadIdx.x;       // [0, 1024*512 + 512*512)
    if (idx < 1024 * 512) {
        int n = idx >> 9, d = idx & 511;
        float w;
        if (n < 512) {
            int hh = n >> 6, k2 = n & 63;
            w = Wq[hh * (512 * 64) + d * 64 + k2];
        } else {
            int nn = n - 512, hh = nn >> 6, k2 = nn & 63;
            w = Wv[hh * (512 * 64) + d * 64 + k2];
        }
        B1[n * 512 + d] = __float2half_rn(w * BSCALE);
    } else {
        int i2 = idx - 1024 * 512;
        int n = i2 >> 9, d = i2 & 511;
        B2[n * 512 + d] = __float2half_rn(Wup[d * 512 + n] * BSCALE);
    }
}

// ====================== HMMA fp16 GEMM =======================================
__device__ __forceinline__ void load_tiles(uint32_t sA, uint32_t sB,
                                           const __half* __restrict__ A,
                                           const __half* __restrict__ B,
                                           int bm, int bn, int ck, int tid) {
    const __half* Ab = A + (size_t)bm * KBIG + ck * 64;
    const __half* Bb = B + (size_t)bn * 512 + (ck & 7) * 64;  // B dup: hi twice
    #pragma unroll
    for (int g = 0; g < 8; g++) {
        int id  = g * 128 + tid;
        int row = id >> 3;
        int c16 = id & 7;
        uint32_t sw = row * 128 + ((c16 * 16) ^ ((row & 7) * 16));
        cp_async16(sA + sw, Ab + (size_t)row * KBIG + c16 * 8);
        cp_async16(sB + sw, Bb + (size_t)row * 512 + c16 * 8);
    }
}

__global__ __launch_bounds__(128)
void gemm_mma(const __half* __restrict__ A,
              const __half* __restrict__ B,
              float* __restrict__ C, int N, float escale) {
    extern __shared__ char smem[];
    uint32_t sb = smem_u32(smem);
    uint32_t SA[3] = {sb, sb + 32768, sb + 65536};
    uint32_t SB[3] = {sb + 16384, sb + 49152, sb + 81920};

    const int tid  = threadIdx.x;
    const int lane = tid & 31;
    const int warp = tid >> 5;
    const int wm   = (warp >> 1) * 64;
    const int wn   = (warp & 1) * 64;
    const int bm   = blockIdx.y * 128, bn = blockIdx.x * 128;

    const int fr = (lane & 7) + ((lane >> 3) & 1) * 8;
    const int fk = (lane >> 4) * 16;

    float acc[4][8][4];
    #pragma unroll
    for (int i = 0; i < 4; i++)
        #pragma unroll
        for (int j = 0; j < 8; j++)
            #pragma unroll
            for (int q = 0; q < 4; q++) acc[i][j][q] = 0.f;

    load_tiles(SA[0], SB[0], A, B, bm, bn, 0, tid); cp_commit();
    load_tiles(SA[1], SB[1], A, B, bm, bn, 1, tid); cp_commit();

    #pragma unroll 1
    for (int c = 0; c < NCHUNK; c++) {
        const int s = c % 3;
        uint32_t sA = SA[s], sBt = SB[s];

        if (c == NCHUNK - 1) cp_wait<0>(); else cp_wait<1>();
        __syncthreads();

        if (c + 2 < NCHUNK) {
            const int s2 = (c + 2) % 3;
            load_tiles(SA[s2], SB[s2], A, B, bm, bn, c + 2, tid);
            cp_commit();
        }

        #pragma unroll
        for (int ks = 0; ks < 4; ks++) {
            const int k0b = ks * 32;
            uint32_t af[4][4], bf[8][2];
            #pragma unroll
            for (int mi = 0; mi < 4; mi++) {
                int r = wm + mi * 16 + fr;
                uint32_t addr = sA + r * 128 + ((k0b + fk) ^ ((r & 7) * 16));
                ldm_x4(af[mi][0], af[mi][1], af[mi][2], af[mi][3], addr);
            }
            #pragma unroll
            for (int ni = 0; ni < 4; ni++) {
                int r = wn + ni * 16 + fr;
                uint32_t addr = sBt + r * 128 + ((k0b + fk) ^ ((r & 7) * 16));
                uint32_t r0, r1, r2, r3;
                ldm_x4(r0, r1, r2, r3, addr);
                bf[2 * ni][0]     = r0; bf[2 * ni][1]     = r2;
                bf[2 * ni + 1][0] = r1; bf[2 * ni + 1][1] = r3;
            }
            #pragma unroll
            for (int mi = 0; mi < 4; mi++)
                #pragma unroll
                for (int nj = 0; nj < 8; nj++)
                    mma16816(acc[mi][nj], af[mi], bf[nj]);
        }
    }

    const int er = lane >> 2;
    const int ec = (lane & 3) * 2;
    #pragma unroll
    for (int mi = 0; mi < 4; mi++) {
        #pragma unroll
        for (int nj = 0; nj < 8; nj++) {
            int row = bm + wm + mi * 16 + er;
            int col = bn + wn + nj * 8 + ec;
            *(float2*)(C + (size_t)row * N + col) =
                make_float2(acc[mi][nj][0] * escale, acc[mi][nj][1] * escale);
            *(float2*)(C + (size_t)(row + 8) * N + col) =
                make_float2(acc[mi][nj][2] * escale, acc[mi][nj][3] * escale);
        }
    }
}

// ============================ band attention (MMA) ===========================
// Block = (b, h, 64-row tile), 256 threads / 8 warps.
// Vband rows r=0..95 (84 real + 12 pad) <-> j = i0-10+r.
// S[64x96] = Q @ Vband^T (mma, K=64). Mask+exp on fragments -> P fp16.
// O[64x64] = P @ Vband (mma over r, K=96, B = VhT). Normalize by rowsum.
#define TILE3   64
#define RB      96
#define PPITCH  104     // halves; 208B rows -> conflict-free ldmatrix

__global__ __launch_bounds__(256)
void band_attn_kernel(const float* __restrict__ QV,
                      __half* __restrict__ A2) {
    __shared__ __half Qh [TILE3 * 64];     //  8 KB, swizzled 128B rows
    __shared__ __half Vh [RB * 64];        // 12 KB, swizzled 128B rows
    __shared__ __half VhT[64 * PPITCH];    // 13 KB, VhT[d][r] = V[r][d]
    __shared__ __half P  [TILE3 * PPITCH]; // 13 KB
    __shared__ float  rowsum[TILE3][2];

    const int bx   = blockIdx.x;
    const int tile = bx & 63;
    const int hd   = (bx >> 6) & 7;
    const int b    = bx >> 9;
    const int i0   = tile * TILE3;
    const int tid  = threadIdx.x;
    const int lane = tid & 31;
    const int warp = tid >> 5;

    const uint32_t sQ  = smem_u32(Qh);
    const uint32_t sV  = smem_u32(Vh);
    const uint32_t sVT = smem_u32(VhT);
    const uint32_t sP  = smem_u32(P);

    // ---- fill Q (scaled by 2^12), swizzled ----
    for (int g = tid; g < TILE3 * 8; g += 256) {
        int r = g >> 3, c16 = g & 7;
        const float* src = QV + (size_t)(b * N_SEQ + i0 + r) * 1024 + hd * 64 + c16 * 8;
        float4 v0 = *(const float4*)src;
        float4 v1 = *(const float4*)(src + 4);
        __half2 h0 = __floats2half2_rn(v0.x * QSCALE, v0.y * QSCALE);
        __half2 h1 = __floats2half2_rn(v0.z * QSCALE, v0.w * QSCALE);
        __half2 h2 = __floats2half2_rn(v1.x * QSCALE, v1.y * QSCALE);
        __half2 h3 = __floats2half2_rn(v1.z * QSCALE, v1.w * QSCALE);
        uint32_t sw = r * 128 + ((c16 * 16) ^ ((r & 7) * 16));
        *(uint4*)((char*)Qh + sw) = make_uint4(h2u(h0), h2u(h1), h2u(h2), h2u(h3));
    }
    // ---- fill Vband (swizzled) + transpose into VhT ----
    for (int g = tid; g < RB * 8; g += 256) {
        int r = g >> 3, c16 = g & 7;
        int j = i0 - CONTEXT + r;
        float4 v0 = make_float4(0.f, 0.f, 0.f, 0.f), v1 = v0;
        if (j >= 0 && j < N_SEQ) {
            const float* src = QV + (size_t)(b * N_SEQ + j) * 1024 + 512 + hd * 64 + c16 * 8;
            v0 = *(const float4*)src;
            v1 = *(const float4*)(src + 4);
        }
        __half h[8];
        h[0] = __float2half_rn(v0.x); h[1] = __float2half_rn(v0.y);
        h[2] = __float2half_rn(v0.z); h[3] = __float2half_rn(v0.w);
        h[4] = __float2half_rn(v1.x); h[5] = __float2half_rn(v1.y);
        h[6] = __float2half_rn(v1.z); h[7] = __float2half_rn(v1.w);
        uint32_t sw = r * 128 + ((c16 * 16) ^ ((r & 7) * 16));
        __half2 p0 = __halves2half2(h[0], h[1]), p1 = __halves2half2(h[2], h[3]);
        __half2 p2 = __halves2half2(h[4], h[5]), p3 = __halves2half2(h[6], h[7]);
        *(uint4*)((char*)Vh + sw) = make_uint4(h2u(p0), h2u(p1), h2u(p2), h2u(p3));
        #pragma unroll
        for (int u = 0; u < 8; u++)
            VhT[(c16 * 8 + u) * PPITCH + r] = h[u];
    }
    __syncthreads();

    const int fr = (lane & 7) + ((lane >> 3) & 1) * 8;
    const int fk = (lane >> 4) * 16;
    const int er = lane >> 2;
    const int ec = (lane & 3) * 2;
    const int rt = warp & 3;        // 16-row tile
    const int ch = warp >> 2;       // 48-col half of the band

    // ---- stage 1: S = Q @ Vband^T (rows rt*16.., cols ch*48..) ----
    float sacc[6][4];
    #pragma unroll
    for (int t = 0; t < 6; t++)
        #pragma unroll
        for (int q = 0; q < 4; q++) sacc[t][q] = 0.f;

    #pragma unroll
    for (int ks = 0; ks < 4; ks++) {
        const int k0b = ks * 32;
        uint32_t af[4], bf[6][2];
        int ar = rt * 16 + fr;
        ldm_x4(af[0], af[1], af[2], af[3],
               sQ + ar * 128 + ((k0b + fk) ^ ((ar & 7) * 16)));
        #pragma unroll
        for (int g = 0; g < 3; g++) {
            int vr = ch * 48 + g * 16 + fr;
            uint32_t r0, r1, r2, r3;
            ldm_x4(r0, r1, r2, r3,
                   sV + vr * 128 + ((k0b + fk) ^ ((vr & 7) * 16)));
            bf[2 * g][0]     = r0; bf[2 * g][1]     = r2;
            bf[2 * g + 1][0] = r1; bf[2 * g + 1][1] = r3;
        }
        #pragma unroll
        for (int t = 0; t < 6; t++)
            mma16816(sacc[t], af, bf[t]);
    }

    // ---- mask + exp -> P, partial row sums ----
    const float sscale = 1.0f / (16.0f * QSCALE);
    float slo = 0.f, shi = 0.f;
    #pragma unroll
    for (int t = 0; t < 6; t++) {
        int cb = ch * 48 + t * 8 + ec;          // band col of pair start
        #pragma unroll
        for (int half = 0; half < 2; half++) {
            int il = rt * 16 + er + half * 8;   // local query row
            float e0 = 0.f, e1 = 0.f;
            int d0 = cb - il, d1 = d0 + 1;
            int j0 = i0 - CONTEXT + cb;
            if (d0 >= 0 && d0 <= 2 * CONTEXT && d0 != CONTEXT &&
                j0 >= 0 && j0 < N_SEQ)
                e0 = __expf(sacc[t][2 * half] * sscale);
            if (d1 >= 0 && d1 <= 2 * CONTEXT && d1 != CONTEXT &&
                j0 + 1 >= 0 && j0 + 1 < N_SEQ)
                e1 = __expf(sacc[t][2 * half + 1] * sscale);
            *(__half2*)&P[il * PPITCH + cb] = __floats2half2_rn(e0, e1);
            if (half == 0) slo += e0 + e1; else shi += e0 + e1;
        }
    }
    slo += __shfl_xor_sync(0xffffffffu, slo, 1);
    slo += __shfl_xor_sync(0xffffffffu, slo, 2);
    shi += __shfl_xor_sync(0xffffffffu, shi, 1);
    shi += __shfl_xor_sync(0xffffffffu, shi, 2);
    if ((lane & 3) == 0) {
        rowsum[rt * 16 + er][ch]     = slo;
        rowsum[rt * 16 + er + 8][ch] = shi;
    }
    __syncthreads();

    // ---- stage 2: O = P @ Vband (K = 96, B = VhT) ----
    const int chd = warp >> 2;      // 32-dim half of the output
    float oacc[4][4];
    #pragma unroll
    for (int t = 0; t < 4; t++)
        #pragma unroll
        for (int q = 0; q < 4; q++) oacc[t][q] = 0.f;

    #pragma unroll
    for (int ks = 0; ks < 6; ks++) {
        const int k0b = ks * 32;
        uint32_t af[4], bf[4][2];
        int ar = rt * 16 + fr;
        ldm_x4(af[0], af[1], af[2], af[3], sP + ar * 208 + k0b + fk);
        #pragma unroll
        for (int g = 0; g < 2; g++) {
            int n = chd * 32 + g * 16 + fr;
            uint32_t r0, r1, r2, r3;
            ldm_x4(r0, r1, r2, r3, sVT + n * 208 + k0b + fk);
            bf[2 * g][0]     = r0; bf[2 * g][1]     = r2;
            bf[2 * g + 1][0] = r1; bf[2 * g + 1][1] = r3;
        }
        #pragma unroll
        for (int t = 0; t < 4; t++)
            mma16816(oacc[t], af, bf[t]);
    }

    // ---- normalize + scaled hi/lo split store ----
    int il0 = rt * 16 + er, il1 = il0 + 8;
    float inv0 = CSCALE / (rowsum[il0][0] + rowsum[il0][1]);
    float inv1 = CSCALE / (rowsum[il1][0] + rowsum[il1][1]);
    #pragma unroll
    for (int t = 0; t < 4; t++) {
        int d = chd * 32 + t * 8 + ec;
        {
            float o0 = oacc[t][0] * inv0, o1 = oacc[t][1] * inv0;
            __half2 h = __floats2half2_rn(o0, o1);
            float2 hf = __half22float2(h);
            __half2 l = __floats2half2_rn(o0 - hf.x, o1 - hf.y);
            __half* cp = A2 + (size_t)(b * N_SEQ + i0 + il0) * KBIG + hd * 64 + d;
            *(__half2*)cp         = h;
            *(__half2*)(cp + 512) = l;
        }
        {
            float o0 = oacc[t][2] * inv1, o1 = oacc[t][3] * inv1;
            __half2 h = __floats2half2_rn(o0, o1);
            float2 hf = __half22float2(h);
            __half2 l = __floats2half2_rn(o0 - hf.x, o1 - hf.y);
            __half* cp = A2 + (size_t)(b * N_SEQ + i0 + il1) * KBIG + hd * 64 + d;
            *(__half2*)cp         = h;
            *(__half2*)(cp + 512) = l;
        }
    }
}

// ================================ launch =====================================
extern "C" void kernel_launch(void* const* d_in, const int* in_sizes, int n_in,
                              void* d_out, int out_size) {
    const float* x   = (const float*)d_in[0];
    const float* Wq  = (const float*)d_in[1];
    const float* Wv  = (const float*)d_in[2];
    const float* Wup = (const float*)d_in[3];
    float* out = (float*)d_out;

    __half *a1, *a2, *b1, *b2;
    float *qv;
    cudaGetSymbolAddress((void**)&a1, g_A1);
    cudaGetSymbolAddress((void**)&a2, g_A2);
    cudaGetSymbolAddress((void**)&b1, g_B1);
    cudaGetSymbolAddress((void**)&b2, g_B2);
    cudaGetSymbolAddress((void**)&qv, g_QV);

    const int SMEM_BYTES = 98304;   // 3 stages x 32KB (gemm)
    cudaFuncSetAttribute(gemm_mma, cudaFuncAttributeMaxDynamicSharedMemorySize,
                         SMEM_BYTES);

    convert_x<<<(M_ROWS * 128) / 256, 256>>>(x, a1);
    repack_b<<<(1024 * 512 + 512 * 512) / 256, 256>>>(Wq, Wv, Wup, b1, b2);

    gemm_mma<<<dim3(1024 / 128, M_ROWS / 128), 128, SMEM_BYTES>>>(
        a1, b1, qv, 1024, 1.0f / BSCALE);
    band_attn_kernel<<<2 * NHEAD * (N_SEQ / TILE3), 256>>>(qv, a2);
    gemm_mma<<<dim3(512 / 128, M_ROWS / 128), 128, SMEM_BYTES>>>(
        a2, b2, out, 512, 1.0f / (BSCALE * CSCALE));
}

// round 12
// speedup vs baseline: 2.5066x; 1.5335x over previous
#include <cuda_runtime.h>
#include <cuda_fp16.h>
#include <cstdint>

// ----------------------------------------------------------------------------
// MultiHeadAttn, pure fp16 tensor-core pipeline (K=512):
//   1) convert_x : x[8192,512] -> A1 fp16 [8192,512]
//   2) repack_b  : Wq,Wv -> B1 fp16 [1024,512]; Wup -> B2 [512,512]  (x 2^13)
//   3) gemm_mma  : QV[8192,1024] fp32 = A1 @ B1^T, escale=2^-13
//   4) band_attn : MMA tiles: S=Q@V^T -> mask+exp -> P -> O=P@V -> C*2^8 fp16
//   5) gemm_mma  : out[8192,512] = A2 @ B2^T, escale=2^-21
// Error sources (each ~2.8e-4 rms, quadrature): x->fp16, C->fp16, Wq/Wv->fp16,
// Wup->fp16  => ~5.5e-4 total, under the 1e-3 bar.
// ----------------------------------------------------------------------------

#define M_ROWS   8192
#define N_SEQ    4096
#define NHEAD    8
#define CONTEXT  10
#define KDIM     512
#define NCHUNK   8           // 512 / 64

#define BSCALE   8192.0f     // 2^13
#define CSCALE   256.0f      // 2^8
#define QSCALE   4096.0f     // 2^12

__device__ __half g_A1[M_ROWS * KDIM];
__device__ __half g_A2[M_ROWS * KDIM];
__device__ __half g_B1[1024 * KDIM];
__device__ __half g_B2[512  * KDIM];
__device__ float  g_QV[M_ROWS * 1024];

// ============================ PTX helpers ====================================
__device__ __forceinline__ uint32_t smem_u32(const void* p) {
    uint32_t a;
    asm("{ .reg .u64 t; cvta.to.shared.u64 t, %1; cvt.u32.u64 %0, t; }"
        : "=r"(a) : "l"(p));
    return a;
}
__device__ __forceinline__ void cp_async16(uint32_t dst, const void* src) {
    asm volatile("cp.async.cg.shared.global [%0], [%1], 16;"
                 :: "r"(dst), "l"(src) : "memory");
}
__device__ __forceinline__ void cp_commit() {
    asm volatile("cp.async.commit_group;" ::: "memory");
}
template <int N>
__device__ __forceinline__ void cp_wait() {
    asm volatile("cp.async.wait_group %0;" :: "n"(N) : "memory");
}
__device__ __forceinline__ void ldm_x4(uint32_t& r0, uint32_t& r1,
                                       uint32_t& r2, uint32_t& r3, uint32_t a) {
    asm volatile("ldmatrix.sync.aligned.m8n8.x4.shared.b16 {%0,%1,%2,%3}, [%4];"
                 : "=r"(r0), "=r"(r1), "=r"(r2), "=r"(r3) : "r"(a));
}
__device__ __forceinline__ void mma16816(float* c, const uint32_t* a,
                                         const uint32_t* b) {
    asm volatile(
        "mma.sync.aligned.m16n8k16.row.col.f32.f16.f16.f32 "
        "{%0,%1,%2,%3}, {%4,%5,%6,%7}, {%8,%9}, {%0,%1,%2,%3};"
        : "+f"(c[0]), "+f"(c[1]), "+f"(c[2]), "+f"(c[3])
        : "r"(a[0]), "r"(a[1]), "r"(a[2]), "r"(a[3]), "r"(b[0]), "r"(b[1]));
}
__device__ __forceinline__ uint32_t h2u(__half2 v) {
    return *reinterpret_cast<uint32_t*>(&v);
}

// ======================= conversion / repack kernels =========================
__global__ void convert_x(const float* __restrict__ x,
                          __half* __restrict__ A1) {
    int idx = blockIdx.x * 256 + threadIdx.x;       // [0, 8192*64)
    int row = idx >> 6;
    int kq  = (idx & 63) * 8;
    const float* src = x + (size_t)row * 512 + kq;
    float4 v0 = *(const float4*)src;
    float4 v1 = *(const float4*)(src + 4);
    __half2 h0 = __floats2half2_rn(v0.x, v0.y);
    __half2 h1 = __floats2half2_rn(v0.z, v0.w);
    __half2 h2 = __floats2half2_rn(v1.x, v1.y);
    __half2 h3 = __floats2half2_rn(v1.z, v1.w);
    *(uint4*)(A1 + (size_t)row * KDIM + kq) =
        make_uint4(h2u(h0), h2u(h1), h2u(h2), h2u(h3));
}

__global__ void repack_b(const float* __restrict__ Wq,
                         const float* __restrict__ Wv,
                         const float* __restrict__ Wup,
                         __half* __restrict__ B1,
                         __half* __restrict__ B2) {
    int idx = blockIdx.x * 256 + threadIdx.x;       // [0, 1024*512 + 512*512)
    if (idx < 1024 * 512) {
        int n = idx >> 9, d = idx & 511;
        float w;
        if (n < 512) {
            int hh = n >> 6, k2 = n & 63;
            w = Wq[hh * (512 * 64) + d * 64 + k2];
        } else {
            int nn = n - 512, hh = nn >> 6, k2 = nn & 63;
            w = Wv[hh * (512 * 64) + d * 64 + k2];
        }
        B1[n * KDIM + d] = __float2half_rn(w * BSCALE);
    } else {
        int i2 = idx - 1024 * 512;
        int n = i2 >> 9, d = i2 & 511;
        B2[n * KDIM + d] = __float2half_rn(Wup[d * 512 + n] * BSCALE);
    }
}

// ====================== HMMA fp16 GEMM (K=512) ===============================
__device__ __forceinline__ void load_tiles(uint32_t sA, uint32_t sB,
                                           const __half* __restrict__ A,
                                           const __half* __restrict__ B,
                                           int bm, int bn, int ck, int tid) {
    const __half* Ab = A + (size_t)bm * KDIM + ck * 64;
    const __half* Bb = B + (size_t)bn * KDIM + ck * 64;
    #pragma unroll
    for (int g = 0; g < 8; g++) {
        int id  = g * 128 + tid;
        int row = id >> 3;
        int c16 = id & 7;
        uint32_t sw = row * 128 + ((c16 * 16) ^ ((row & 7) * 16));
        cp_async16(sA + sw, Ab + (size_t)row * KDIM + c16 * 8);
        cp_async16(sB + sw, Bb + (size_t)row * KDIM + c16 * 8);
    }
}

__global__ __launch_bounds__(128)
void gemm_mma(const __half* __restrict__ A,
              const __half* __restrict__ B,
              float* __restrict__ C, int N, float escale) {
    extern __shared__ char smem[];
    uint32_t sb = smem_u32(smem);
    uint32_t SA[3] = {sb, sb + 32768, sb + 65536};
    uint32_t SB[3] = {sb + 16384, sb + 49152, sb + 81920};

    const int tid  = threadIdx.x;
    const int lane = tid & 31;
    const int warp = tid >> 5;
    const int wm   = (warp >> 1) * 64;
    const int wn   = (warp & 1) * 64;
    const int bm   = blockIdx.y * 128, bn = blockIdx.x * 128;

    const int fr = (lane & 7) + ((lane >> 3) & 1) * 8;
    const int fk = (lane >> 4) * 16;

    float acc[4][8][4];
    #pragma unroll
    for (int i = 0; i < 4; i++)
        #pragma unroll
        for (int j = 0; j < 8; j++)
            #pragma unroll
            for (int q = 0; q < 4; q++) acc[i][j][q] = 0.f;

    load_tiles(SA[0], SB[0], A, B, bm, bn, 0, tid); cp_commit();
    load_tiles(SA[1], SB[1], A, B, bm, bn, 1, tid); cp_commit();

    #pragma unroll 1
    for (int c = 0; c < NCHUNK; c++) {
        const int s = c % 3;
        uint32_t sA = SA[s], sBt = SB[s];

        if (c == NCHUNK - 1) cp_wait<0>(); else cp_wait<1>();
        __syncthreads();

        if (c + 2 < NCHUNK) {
            const int s2 = (c + 2) % 3;
            load_tiles(SA[s2], SB[s2], A, B, bm, bn, c + 2, tid);
            cp_commit();
        }

        #pragma unroll
        for (int ks = 0; ks < 4; ks++) {
            const int k0b = ks * 32;
            uint32_t af[4][4], bf[8][2];
            #pragma unroll
            for (int mi = 0; mi < 4; mi++) {
                int r = wm + mi * 16 + fr;
                uint32_t addr = sA + r * 128 + ((k0b + fk) ^ ((r & 7) * 16));
                ldm_x4(af[mi][0], af[mi][1], af[mi][2], af[mi][3], addr);
            }
            #pragma unroll
            for (int ni = 0; ni < 4; ni++) {
                int r = wn + ni * 16 + fr;
                uint32_t addr = sBt + r * 128 + ((k0b + fk) ^ ((r & 7) * 16));
                uint32_t r0, r1, r2, r3;
                ldm_x4(r0, r1, r2, r3, addr);
                bf[2 * ni][0]     = r0; bf[2 * ni][1]     = r2;
                bf[2 * ni + 1][0] = r1; bf[2 * ni + 1][1] = r3;
            }
            #pragma unroll
            for (int mi = 0; mi < 4; mi++)
                #pragma unroll
                for (int nj = 0; nj < 8; nj++)
                    mma16816(acc[mi][nj], af[mi], bf[nj]);
        }
    }

    const int er = lane >> 2;
    const int ec = (lane & 3) * 2;
    #pragma unroll
    for (int mi = 0; mi < 4; mi++) {
        #pragma unroll
        for (int nj = 0; nj < 8; nj++) {
            int row = bm + wm + mi * 16 + er;
            int col = bn + wn + nj * 8 + ec;
            *(float2*)(C + (size_t)row * N + col) =
                make_float2(acc[mi][nj][0] * escale, acc[mi][nj][1] * escale);
            *(float2*)(C + (size_t)(row + 8) * N + col) =
                make_float2(acc[mi][nj][2] * escale, acc[mi][nj][3] * escale);
        }
    }
}

// ============================ band attention (MMA) ===========================
// Block = (b, h, 64-row tile), 256 threads / 8 warps.
// Vband rows r=0..95 (84 real + 12 pad) <-> j = i0-10+r.
// S[64x96] = Q @ Vband^T (mma, K=64). Mask+exp on fragments -> P fp16.
// O[64x64] = P @ Vband (mma over r, K=96, B = VhT). Normalize by rowsum.
#define TILE3   64
#define RB      96
#define PPITCH  104     // halves; 208B rows -> conflict-free ldmatrix

__global__ __launch_bounds__(256)
void band_attn_kernel(const float* __restrict__ QV,
                      __half* __restrict__ A2) {
    __shared__ __half Qh [TILE3 * 64];     //  8 KB, swizzled 128B rows
    __shared__ __half Vh [RB * 64];        // 12 KB, swizzled 128B rows
    __shared__ __half VhT[64 * PPITCH];    // 13 KB, VhT[d][r] = V[r][d]
    __shared__ __half P  [TILE3 * PPITCH]; // 13 KB
    __shared__ float  rowsum[TILE3][2];

    const int bx   = blockIdx.x;
    const int tile = bx & 63;
    const int hd   = (bx >> 6) & 7;
    const int b    = bx >> 9;
    const int i0   = tile * TILE3;
    const int tid  = threadIdx.x;
    const int lane = tid & 31;
    const int warp = tid >> 5;

    const uint32_t sQ  = smem_u32(Qh);
    const uint32_t sV  = smem_u32(Vh);
    const uint32_t sVT = smem_u32(VhT);
    const uint32_t sP  = smem_u32(P);

    // ---- fill Q (scaled by 2^12), swizzled ----
    for (int g = tid; g < TILE3 * 8; g += 256) {
        int r = g >> 3, c16 = g & 7;
        const float* src = QV + (size_t)(b * N_SEQ + i0 + r) * 1024 + hd * 64 + c16 * 8;
        float4 v0 = *(const float4*)src;
        float4 v1 = *(const float4*)(src + 4);
        __half2 h0 = __floats2half2_rn(v0.x * QSCALE, v0.y * QSCALE);
        __half2 h1 = __floats2half2_rn(v0.z * QSCALE, v0.w * QSCALE);
        __half2 h2 = __floats2half2_rn(v1.x * QSCALE, v1.y * QSCALE);
        __half2 h3 = __floats2half2_rn(v1.z * QSCALE, v1.w * QSCALE);
        uint32_t sw = r * 128 + ((c16 * 16) ^ ((r & 7) * 16));
        *(uint4*)((char*)Qh + sw) = make_uint4(h2u(h0), h2u(h1), h2u(h2), h2u(h3));
    }
    // ---- fill Vband (swizzled) + transpose into VhT ----
    for (int g = tid; g < RB * 8; g += 256) {
        int r = g >> 3, c16 = g & 7;
        int j = i0 - CONTEXT + r;
        float4 v0 = make_float4(0.f, 0.f, 0.f, 0.f), v1 = v0;
        if (j >= 0 && j < N_SEQ) {
            const float* src = QV + (size_t)(b * N_SEQ + j) * 1024 + 512 + hd * 64 + c16 * 8;
            v0 = *(const float4*)src;
            v1 = *(const float4*)(src + 4);
        }
        __half h[8];
        h[0] = __float2half_rn(v0.x); h[1] = __float2half_rn(v0.y);
        h[2] = __float2half_rn(v0.z); h[3] = __float2half_rn(v0.w);
        h[4] = __float2half_rn(v1.x); h[5] = __float2half_rn(v1.y);
        h[6] = __float2half_rn(v1.z); h[7] = __float2half_rn(v1.w);
        uint32_t sw = r * 128 + ((c16 * 16) ^ ((r & 7) * 16));
        __half2 p0 = __halves2half2(h[0], h[1]), p1 = __halves2half2(h[2], h[3]);
        __half2 p2 = __halves2half2(h[4], h[5]), p3 = __halves2half2(h[6], h[7]);
        *(uint4*)((char*)Vh + sw) = make_uint4(h2u(p0), h2u(p1), h2u(p2), h2u(p3));
        #pragma unroll
        for (int u = 0; u < 8; u++)
            VhT[(c16 * 8 + u) * PPITCH + r] = h[u];
    }
    __syncthreads();

    const int fr = (lane & 7) + ((lane >> 3) & 1) * 8;
    const int fk = (lane >> 4) * 16;
    const int er = lane >> 2;
    const int ec = (lane & 3) * 2;
    const int rt = warp & 3;        // 16-row tile
    const int ch = warp >> 2;       // 48-col half of the band

    // ---- stage 1: S = Q @ Vband^T ----
    float sacc[6][4];
    #pragma unroll
    for (int t = 0; t < 6; t++)
        #pragma unroll
        for (int q = 0; q < 4; q++) sacc[t][q] = 0.f;

    #pragma unroll
    for (int ks = 0; ks < 4; ks++) {
        const int k0b = ks * 32;
        uint32_t af[4], bf[6][2];
        int ar = rt * 16 + fr;
        ldm_x4(af[0], af[1], af[2], af[3],
               sQ + ar * 128 + ((k0b + fk) ^ ((ar & 7) * 16)));
        #pragma unroll
        for (int g = 0; g < 3; g++) {
            int vr = ch * 48 + g * 16 + fr;
            uint32_t r0, r1, r2, r3;
            ldm_x4(r0, r1, r2, r3,
                   sV + vr * 128 + ((k0b + fk) ^ ((vr & 7) * 16)));
            bf[2 * g][0]     = r0; bf[2 * g][1]     = r2;
            bf[2 * g + 1][0] = r1; bf[2 * g + 1][1] = r3;
        }
        #pragma unroll
        for (int t = 0; t < 6; t++)
            mma16816(sacc[t], af, bf[t]);
    }

    // ---- mask + exp -> P, partial row sums ----
    const float sscale = 1.0f / (16.0f * QSCALE);
    float slo = 0.f, shi = 0.f;
    #pragma unroll
    for (int t = 0; t < 6; t++) {
        int cb = ch * 48 + t * 8 + ec;
        #pragma unroll
        for (int half = 0; half < 2; half++) {
            int il = rt * 16 + er + half * 8;
            float e0 = 0.f, e1 = 0.f;
            int d0 = cb - il, d1 = d0 + 1;
            int j0 = i0 - CONTEXT + cb;
            if (d0 >= 0 && d0 <= 2 * CONTEXT && d0 != CONTEXT &&
                j0 >= 0 && j0 < N_SEQ)
                e0 = __expf(sacc[t][2 * half] * sscale);
            if (d1 >= 0 && d1 <= 2 * CONTEXT && d1 != CONTEXT &&
                j0 + 1 >= 0 && j0 + 1 < N_SEQ)
                e1 = __expf(sacc[t][2 * half + 1] * sscale);
            *(__half2*)&P[il * PPITCH + cb] = __floats2half2_rn(e0, e1);
            if (half == 0) slo += e0 + e1; else shi += e0 + e1;
        }
    }
    slo += __shfl_xor_sync(0xffffffffu, slo, 1);
    slo += __shfl_xor_sync(0xffffffffu, slo, 2);
    shi += __shfl_xor_sync(0xffffffffu, shi, 1);
    shi += __shfl_xor_sync(0xffffffffu, shi, 2);
    if ((lane & 3) == 0) {
        rowsum[rt * 16 + er][ch]     = slo;
        rowsum[rt * 16 + er + 8][ch] = shi;
    }
    __syncthreads();

    // ---- stage 2: O = P @ Vband (K = 96, B = VhT) ----
    const int chd = warp >> 2;
    float oacc[4][4];
    #pragma unroll
    for (int t = 0; t < 4; t++)
        #pragma unroll
        for (int q = 0; q < 4; q++) oacc[t][q] = 0.f;

    #pragma unroll
    for (int ks = 0; ks < 6; ks++) {
        const int k0b = ks * 32;
        uint32_t af[4], bf[4][2];
        int ar = rt * 16 + fr;
        ldm_x4(af[0], af[1], af[2], af[3], sP + ar * 208 + k0b + fk);
        #pragma unroll
        for (int g = 0; g < 2; g++) {
            int n = chd * 32 + g * 16 + fr;
            uint32_t r0, r1, r2, r3;
            ldm_x4(r0, r1, r2, r3, sVT + n * 208 + k0b + fk);
            bf[2 * g][0]     = r0; bf[2 * g][1]     = r2;
            bf[2 * g + 1][0] = r1; bf[2 * g + 1][1] = r3;
        }
        #pragma unroll
        for (int t = 0; t < 4; t++)
            mma16816(oacc[t], af, bf[t]);
    }

    // ---- normalize + store C*2^8 as fp16 ----
    int il0 = rt * 16 + er, il1 = il0 + 8;
    float inv0 = CSCALE / (rowsum[il0][0] + rowsum[il0][1]);
    float inv1 = CSCALE / (rowsum[il1][0] + rowsum[il1][1]);
    #pragma unroll
    for (int t = 0; t < 4; t++) {
        int d = chd * 32 + t * 8 + ec;
        {
            __half2 h = __floats2half2_rn(oacc[t][0] * inv0, oacc[t][1] * inv0);
            *(__half2*)(A2 + (size_t)(b * N_SEQ + i0 + il0) * KDIM + hd * 64 + d) = h;
        }
        {
            __half2 h = __floats2half2_rn(oacc[t][2] * inv1, oacc[t][3] * inv1);
            *(__half2*)(A2 + (size_t)(b * N_SEQ + i0 + il1) * KDIM + hd * 64 + d) = h;
        }
    }
}

// ================================ launch =====================================
extern "C" void kernel_launch(void* const* d_in, const int* in_sizes, int n_in,
                              void* d_out, int out_size) {
    const float* x   = (const float*)d_in[0];
    const float* Wq  = (const float*)d_in[1];
    const float* Wv  = (const float*)d_in[2];
    const float* Wup = (const float*)d_in[3];
    float* out = (float*)d_out;

    __half *a1, *a2, *b1, *b2;
    float *qv;
    cudaGetSymbolAddress((void**)&a1, g_A1);
    cudaGetSymbolAddress((void**)&a2, g_A2);
    cudaGetSymbolAddress((void**)&b1, g_B1);
    cudaGetSymbolAddress((void**)&b2, g_B2);
    cudaGetSymbolAddress((void**)&qv, g_QV);

    const int SMEM_BYTES = 98304;   // 3 stages x 32KB (gemm)
    cudaFuncSetAttribute(gemm_mma, cudaFuncAttributeMaxDynamicSharedMemorySize,
                         SMEM_BYTES);

    convert_x<<<(M_ROWS * 64) / 256, 256>>>(x, a1);
    repack_b<<<(1024 * 512 + 512 * 512) / 256, 256>>>(Wq, Wv, Wup, b1, b2);

    gemm_mma<<<dim3(1024 / 128, M_ROWS / 128), 128, SMEM_BYTES>>>(
        a1, b1, qv, 1024, 1.0f / BSCALE);
    band_attn_kernel<<<2 * NHEAD * (N_SEQ / TILE3), 256>>>(qv, a2);
    gemm_mma<<<dim3(512 / 128, M_ROWS / 128), 128, SMEM_BYTES>>>(
        a2, b2, out, 512, 1.0f / (BSCALE * CSCALE));
}

// round 13
// speedup vs baseline: 2.7678x; 1.1042x over previous
#include <cuda_runtime.h>
#include <cuda_fp16.h>
#include <cstdint>

// ----------------------------------------------------------------------------
// MultiHeadAttn, pure fp16 tensor-core pipeline (K=512):
//   1) convert_x : x[8192,512] -> A1 fp16 [8192,512]
//   2) repack_b  : Wq,Wv -> B1 fp16 [1024,512]; Wup -> B2 [512,512]  (x 2^13)
//   3) gemm_mma  : QV[8192,1024] fp32 = A1 @ B1^T, escale=2^-13
//   4) band_attn v3: 128-row tiles, per-warp 16x48 diagonal window,
//      S=Q@V^T (mma) -> mask+exp -> P -> O=P@V (ldmatrix.trans B) -> C*2^8
//   5) gemm_mma  : out[8192,512] = A2 @ B2^T, escale=2^-21
// ----------------------------------------------------------------------------

#define M_ROWS   8192
#define N_SEQ    4096
#define NHEAD    8
#define CONTEXT  10
#define KDIM     512
#define NCHUNK   8           // 512 / 64

#define BSCALE   8192.0f     // 2^13
#define CSCALE   256.0f      // 2^8
#define QSCALE   4096.0f     // 2^12

__device__ __half g_A1[M_ROWS * KDIM];
__device__ __half g_A2[M_ROWS * KDIM];
__device__ __half g_B1[1024 * KDIM];
__device__ __half g_B2[512  * KDIM];
__device__ float  g_QV[M_ROWS * 1024];

// ============================ PTX helpers ====================================
__device__ __forceinline__ uint32_t smem_u32(const void* p) {
    uint32_t a;
    asm("{ .reg .u64 t; cvta.to.shared.u64 t, %1; cvt.u32.u64 %0, t; }"
        : "=r"(a) : "l"(p));
    return a;
}
__device__ __forceinline__ void cp_async16(uint32_t dst, const void* src) {
    asm volatile("cp.async.cg.shared.global [%0], [%1], 16;"
                 :: "r"(dst), "l"(src) : "memory");
}
__device__ __forceinline__ void cp_commit() {
    asm volatile("cp.async.commit_group;" ::: "memory");
}
template <int N>
__device__ __forceinline__ void cp_wait() {
    asm volatile("cp.async.wait_group %0;" :: "n"(N) : "memory");
}
__device__ __forceinline__ void ldm_x4(uint32_t& r0, uint32_t& r1,
                                       uint32_t& r2, uint32_t& r3, uint32_t a) {
    asm volatile("ldmatrix.sync.aligned.m8n8.x4.shared.b16 {%0,%1,%2,%3}, [%4];"
                 : "=r"(r0), "=r"(r1), "=r"(r2), "=r"(r3) : "r"(a));
}
__device__ __forceinline__ void ldm_x4_t(uint32_t& r0, uint32_t& r1,
                                         uint32_t& r2, uint32_t& r3, uint32_t a) {
    asm volatile("ldmatrix.sync.aligned.m8n8.x4.trans.shared.b16 {%0,%1,%2,%3}, [%4];"
                 : "=r"(r0), "=r"(r1), "=r"(r2), "=r"(r3) : "r"(a));
}
__device__ __forceinline__ void mma16816(float* c, const uint32_t* a,
                                         const uint32_t* b) {
    asm volatile(
        "mma.sync.aligned.m16n8k16.row.col.f32.f16.f16.f32 "
        "{%0,%1,%2,%3}, {%4,%5,%6,%7}, {%8,%9}, {%0,%1,%2,%3};"
        : "+f"(c[0]), "+f"(c[1]), "+f"(c[2]), "+f"(c[3])
        : "r"(a[0]), "r"(a[1]), "r"(a[2]), "r"(a[3]), "r"(b[0]), "r"(b[1]));
}
__device__ __forceinline__ uint32_t h2u(__half2 v) {
    return *reinterpret_cast<uint32_t*>(&v);
}

// ======================= conversion / repack kernels =========================
__global__ void convert_x(const float* __restrict__ x,
                          __half* __restrict__ A1) {
    int idx = blockIdx.x * 256 + threadIdx.x;       // [0, 8192*64)
    int row = idx >> 6;
    int kq  = (idx & 63) * 8;
    const float* src = x + (size_t)row * 512 + kq;
    float4 v0 = *(const float4*)src;
    float4 v1 = *(const float4*)(src + 4);
    __half2 h0 = __floats2half2_rn(v0.x, v0.y);
    __half2 h1 = __floats2half2_rn(v0.z, v0.w);
    __half2 h2 = __floats2half2_rn(v1.x, v1.y);
    __half2 h3 = __floats2half2_rn(v1.z, v1.w);
    *(uint4*)(A1 + (size_t)row * KDIM + kq) =
        make_uint4(h2u(h0), h2u(h1), h2u(h2), h2u(h3));
}

__global__ void repack_b(const float* __restrict__ Wq,
                         const float* __restrict__ Wv,
                         const float* __restrict__ Wup,
                         __half* __restrict__ B1,
                         __half* __restrict__ B2) {
    int idx = blockIdx.x * 256 + threadIdx.x;       // [0, 1024*512 + 512*512)
    if (idx < 1024 * 512) {
        int n = idx >> 9, d = idx & 511;
        float w;
        if (n < 512) {
            int hh = n >> 6, k2 = n & 63;
            w = Wq[hh * (512 * 64) + d * 64 + k2];
        } else {
            int nn = n - 512, hh = nn >> 6, k2 = nn & 63;
            w = Wv[hh * (512 * 64) + d * 64 + k2];
        }
        B1[n * KDIM + d] = __float2half_rn(w * BSCALE);
    } else {
        int i2 = idx - 1024 * 512;
        int n = i2 >> 9, d = i2 & 511;
        B2[n * KDIM + d] = __float2half_rn(Wup[d * 512 + n] * BSCALE);
    }
}

// ====================== HMMA fp16 GEMM (K=512) ===============================
__device__ __forceinline__ void load_tiles(uint32_t sA, uint32_t sB,
                                           const __half* __restrict__ A,
                                           const __half* __restrict__ B,
                                           int bm, int bn, int ck, int tid) {
    const __half* Ab = A + (size_t)bm * KDIM + ck * 64;
    const __half* Bb = B + (size_t)bn * KDIM + ck * 64;
    #pragma unroll
    for (int g = 0; g < 8; g++) {
        int id  = g * 128 + tid;
        int row = id >> 3;
        int c16 = id & 7;
        uint32_t sw = row * 128 + ((c16 * 16) ^ ((row & 7) * 16));
        cp_async16(sA + sw, Ab + (size_t)row * KDIM + c16 * 8);
        cp_async16(sB + sw, Bb + (size_t)row * KDIM + c16 * 8);
    }
}

__global__ __launch_bounds__(128)
void gemm_mma(const __half* __restrict__ A,
              const __half* __restrict__ B,
              float* __restrict__ C, int N, float escale) {
    extern __shared__ char smem[];
    uint32_t sb = smem_u32(smem);
    uint32_t SA[3] = {sb, sb + 32768, sb + 65536};
    uint32_t SB[3] = {sb + 16384, sb + 49152, sb + 81920};

    const int tid  = threadIdx.x;
    const int lane = tid & 31;
    const int warp = tid >> 5;
    const int wm   = (warp >> 1) * 64;
    const int wn   = (warp & 1) * 64;
    const int bm   = blockIdx.y * 128, bn = blockIdx.x * 128;

    const int fr = (lane & 7) + ((lane >> 3) & 1) * 8;
    const int fk = (lane >> 4) * 16;

    float acc[4][8][4];
    #pragma unroll
    for (int i = 0; i < 4; i++)
        #pragma unroll
        for (int j = 0; j < 8; j++)
            #pragma unroll
            for (int q = 0; q < 4; q++) acc[i][j][q] = 0.f;

    load_tiles(SA[0], SB[0], A, B, bm, bn, 0, tid); cp_commit();
    load_tiles(SA[1], SB[1], A, B, bm, bn, 1, tid); cp_commit();

    #pragma unroll 1
    for (int c = 0; c < NCHUNK; c++) {
        const int s = c % 3;
        uint32_t sA = SA[s], sBt = SB[s];

        if (c == NCHUNK - 1) cp_wait<0>(); else cp_wait<1>();
        __syncthreads();

        if (c + 2 < NCHUNK) {
            const int s2 = (c + 2) % 3;
            load_tiles(SA[s2], SB[s2], A, B, bm, bn, c + 2, tid);
            cp_commit();
        }

        #pragma unroll
        for (int ks = 0; ks < 4; ks++) {
            const int k0b = ks * 32;
            uint32_t af[4][4], bf[8][2];
            #pragma unroll
            for (int mi = 0; mi < 4; mi++) {
                int r = wm + mi * 16 + fr;
                uint32_t addr = sA + r * 128 + ((k0b + fk) ^ ((r & 7) * 16));
                ldm_x4(af[mi][0], af[mi][1], af[mi][2], af[mi][3], addr);
            }
            #pragma unroll
            for (int ni = 0; ni < 4; ni++) {
                int r = wn + ni * 16 + fr;
                uint32_t addr = sBt + r * 128 + ((k0b + fk) ^ ((r & 7) * 16));
                uint32_t r0, r1, r2, r3;
                ldm_x4(r0, r1, r2, r3, addr);
                bf[2 * ni][0]     = r0; bf[2 * ni][1]     = r2;
                bf[2 * ni + 1][0] = r1; bf[2 * ni + 1][1] = r3;
            }
            #pragma unroll
            for (int mi = 0; mi < 4; mi++)
                #pragma unroll
                for (int nj = 0; nj < 8; nj++)
                    mma16816(acc[mi][nj], af[mi], bf[nj]);
        }
    }

    const int er = lane >> 2;
    const int ec = (lane & 3) * 2;
    #pragma unroll
    for (int mi = 0; mi < 4; mi++) {
        #pragma unroll
        for (int nj = 0; nj < 8; nj++) {
            int row = bm + wm + mi * 16 + er;
            int col = bn + wn + nj * 8 + ec;
            *(float2*)(C + (size_t)row * N + col) =
                make_float2(acc[mi][nj][0] * escale, acc[mi][nj][1] * escale);
            *(float2*)(C + (size_t)(row + 8) * N + col) =
                make_float2(acc[mi][nj][2] * escale, acc[mi][nj][3] * escale);
        }
    }
}

// ========================= band attention v3 (MMA) ===========================
// Block = (b, h, 128-row tile), 256 threads / 8 warps; warp rt owns rows
// [16rt, 16rt+16) whose band cols fall in window [16rt, 16rt+48).
// Vband rows r=0..159 <-> j = i0-10+r (zero-filled out of range).
// Stage 1: S[16x48] = Q @ V^T (mma, K=64).  mask+exp -> P (local 48 cols).
// Stage 2: O[16x64] = P @ V (K=48 from 16rt; B via ldmatrix.x4.trans on Vh).
#define TILE4   128
#define RB4     160
#define PP4     56          // P pitch in halves (112B rows; conflict-free)
#define SM_Q    0
#define SM_V    16384
#define SM_P    36864
#define SM_TOT  51200       // 16K Q + 20K V + 14K P

__global__ __launch_bounds__(256)
void band_attn_kernel(const float* __restrict__ QV,
                      __half* __restrict__ A2) {
    extern __shared__ char bsm[];
    const uint32_t sQ = smem_u32(bsm);
    const uint32_t sV = sQ + SM_V;
    const uint32_t sP = sQ + SM_P;
    __half* Ph = (__half*)(bsm + SM_P);

    const int bx   = blockIdx.x;          // [0, 512)
    const int tile = bx & 31;
    const int hd   = (bx >> 5) & 7;
    const int b    = bx >> 8;
    const int i0   = tile * TILE4;
    const int tid  = threadIdx.x;
    const int lane = tid & 31;
    const int rt   = tid >> 5;            // warp = row tile 0..7

    // ---- fill Q (scaled 2^12), swizzled 128B rows ----
    for (int g = tid; g < TILE4 * 8; g += 256) {
        int r = g >> 3, c16 = g & 7;
        const float* src = QV + (size_t)(b * N_SEQ + i0 + r) * 1024 + hd * 64 + c16 * 8;
        float4 v0 = *(const float4*)src;
        float4 v1 = *(const float4*)(src + 4);
        __half2 h0 = __floats2half2_rn(v0.x * QSCALE, v0.y * QSCALE);
        __half2 h1 = __floats2half2_rn(v0.z * QSCALE, v0.w * QSCALE);
        __half2 h2 = __floats2half2_rn(v1.x * QSCALE, v1.y * QSCALE);
        __half2 h3 = __floats2half2_rn(v1.z * QSCALE, v1.w * QSCALE);
        uint32_t sw = r * 128 + ((c16 * 16) ^ ((r & 7) * 16));
        *(uint4*)(bsm + SM_Q + sw) = make_uint4(h2u(h0), h2u(h1), h2u(h2), h2u(h3));
    }
    // ---- fill V band rows, swizzled (no transpose buffer) ----
    for (int g = tid; g < RB4 * 8; g += 256) {
        int r = g >> 3, c16 = g & 7;
        int j = i0 - CONTEXT + r;
        float4 v0 = make_float4(0.f, 0.f, 0.f, 0.f), v1 = v0;
        if (j >= 0 && j < N_SEQ) {
            const float* src = QV + (size_t)(b * N_SEQ + j) * 1024 + 512 + hd * 64 + c16 * 8;
            v0 = *(const float4*)src;
            v1 = *(const float4*)(src + 4);
        }
        __half2 p0 = __floats2half2_rn(v0.x, v0.y);
        __half2 p1 = __floats2half2_rn(v0.z, v0.w);
        __half2 p2 = __floats2half2_rn(v1.x, v1.y);
        __half2 p3 = __floats2half2_rn(v1.z, v1.w);
        uint32_t sw = r * 128 + ((c16 * 16) ^ ((r & 7) * 16));
        *(uint4*)(bsm + SM_V + sw) = make_uint4(h2u(p0), h2u(p1), h2u(p2), h2u(p3));
    }
    __syncthreads();

    const int fr = (lane & 7) + ((lane >> 3) & 1) * 8;
    const int fk = (lane >> 4) * 16;
    const int er = lane >> 2;
    const int ec = (lane & 3) * 2;
    const int rb = rt * 16;               // row/window base

    // ---- stage 1: S[16x48] = Q @ V^T over window ----
    float sacc[6][4];
    #pragma unroll
    for (int t = 0; t < 6; t++)
        #pragma unroll
        for (int q = 0; q < 4; q++) sacc[t][q] = 0.f;

    #pragma unroll
    for (int ks = 0; ks < 4; ks++) {
        const int k0b = ks * 32;
        uint32_t af[4], bf[6][2];
        int ar = rb + fr;
        ldm_x4(af[0], af[1], af[2], af[3],
               sQ + ar * 128 + ((k0b + fk) ^ ((ar & 7) * 16)));
        #pragma unroll
        for (int g = 0; g < 3; g++) {
            int vr = rb + g * 16 + fr;
            uint32_t r0, r1, r2, r3;
            ldm_x4(r0, r1, r2, r3,
                   sV + vr * 128 + ((k0b + fk) ^ ((vr & 7) * 16)));
            bf[2 * g][0]     = r0; bf[2 * g][1]     = r2;
            bf[2 * g + 1][0] = r1; bf[2 * g + 1][1] = r3;
        }
        #pragma unroll
        for (int t = 0; t < 6; t++)
            mma16816(sacc[t], af, bf[t]);
    }

    // ---- mask + exp -> P (local cols), rowsums in registers ----
    const float sscale = 1.0f / (16.0f * QSCALE);
    float slo = 0.f, shi = 0.f;
    #pragma unroll
    for (int t = 0; t < 6; t++) {
        int lc = t * 8 + ec;                    // local window col
        #pragma unroll
        for (int half = 0; half < 2; half++) {
            int rl = er + half * 8;             // row within warp tile
            float e0 = 0.f, e1 = 0.f;
            int d0 = lc - rl, d1 = d0 + 1;
            int j0 = i0 - CONTEXT + rb + lc;
            if (d0 >= 0 && d0 <= 2 * CONTEXT && d0 != CONTEXT &&
                j0 >= 0 && j0 < N_SEQ)
                e0 = __expf(sacc[t][2 * half] * sscale);
            if (d1 >= 0 && d1 <= 2 * CONTEXT && d1 != CONTEXT &&
                j0 + 1 >= 0 && j0 + 1 < N_SEQ)
                e1 = __expf(sacc[t][2 * half + 1] * sscale);
            *(__half2*)&Ph[(rb + rl) * PP4 + lc] = __floats2half2_rn(e0, e1);
            if (half == 0) slo += e0 + e1; else shi += e0 + e1;
        }
    }
    slo += __shfl_xor_sync(0xffffffffu, slo, 1);
    slo += __shfl_xor_sync(0xffffffffu, slo, 2);
    shi += __shfl_xor_sync(0xffffffffu, shi, 1);
    shi += __shfl_xor_sync(0xffffffffu, shi, 2);
    __syncwarp();          // P rows of this warp visible to its own ldmatrix

    // ---- stage 2: O[16x64] = P @ V (K = 48, B via trans ldmatrix) ----
    float oacc[8][4];
    #pragma unroll
    for (int t = 0; t < 8; t++)
        #pragma unroll
        for (int q = 0; q < 4; q++) oacc[t][q] = 0.f;

    #pragma unroll
    for (int ks = 0; ks < 3; ks++) {
        uint32_t af[4], bf[8][2];
        int ar = rb + fr;
        ldm_x4(af[0], af[1], af[2], af[3], sP + ar * 112 + ks * 32 + fk);
        #pragma unroll
        for (int g = 0; g < 4; g++) {
            int vr = rb + ks * 16 + fr;          // k index (band row)
            uint32_t nb = g * 32 + fk;           // n (dim) byte offset
            uint32_t r0, r1, r2, r3;
            ldm_x4_t(r0, r1, r2, r3,
                     sV + vr * 128 + (nb ^ ((vr & 7) * 16)));
            bf[2 * g][0]     = r0; bf[2 * g][1]     = r1;
            bf[2 * g + 1][0] = r2; bf[2 * g + 1][1] = r3;
        }
        #pragma unroll
        for (int t = 0; t < 8; t++)
            mma16816(oacc[t], af, bf[t]);
    }

    // ---- normalize + store C*2^8 as fp16 ----
    float inv0 = CSCALE / slo;
    float inv1 = CSCALE / shi;
    int il0 = i0 + rb + er, il1 = il0 + 8;
    #pragma unroll
    for (int t = 0; t < 8; t++) {
        int d = t * 8 + ec;
        __half2 h0 = __floats2half2_rn(oacc[t][0] * inv0, oacc[t][1] * inv0);
        __half2 h1 = __floats2half2_rn(oacc[t][2] * inv1, oacc[t][3] * inv1);
        *(__half2*)(A2 + (size_t)(b * N_SEQ + il0) * KDIM + hd * 64 + d) = h0;
        *(__half2*)(A2 + (size_t)(b * N_SEQ + il1) * KDIM + hd * 64 + d) = h1;
    }
}

// ================================ launch =====================================
extern "C" void kernel_launch(void* const* d_in, const int* in_sizes, int n_in,
                              void* d_out, int out_size) {
    const float* x   = (const float*)d_in[0];
    const float* Wq  = (const float*)d_in[1];
    const float* Wv  = (const float*)d_in[2];
    const float* Wup = (const float*)d_in[3];
    float* out = (float*)d_out;

    __half *a1, *a2, *b1, *b2;
    float *qv;
    cudaGetSymbolAddress((void**)&a1, g_A1);
    cudaGetSymbolAddress((void**)&a2, g_A2);
    cudaGetSymbolAddress((void**)&b1, g_B1);
    cudaGetSymbolAddress((void**)&b2, g_B2);
    cudaGetSymbolAddress((void**)&qv, g_QV);

    const int SMEM_BYTES = 98304;   // 3 stages x 32KB (gemm)
    cudaFuncSetAttribute(gemm_mma, cudaFuncAttributeMaxDynamicSharedMemorySize,
                         SMEM_BYTES);
    cudaFuncSetAttribute(band_attn_kernel,
                         cudaFuncAttributeMaxDynamicSharedMemorySize, SM_TOT);

    convert_x<<<(M_ROWS * 64) / 256, 256>>>(x, a1);
    repack_b<<<(1024 * 512 + 512 * 512) / 256, 256>>>(Wq, Wv, Wup, b1, b2);

    gemm_mma<<<dim3(1024 / 128, M_ROWS / 128), 128, SMEM_BYTES>>>(
        a1, b1, qv, 1024, 1.0f / BSCALE);
    band_attn_kernel<<<2 * NHEAD * (N_SEQ / TILE4), 256, SM_TOT>>>(qv, a2);
    gemm_mma<<<dim3(512 / 128, M_ROWS / 128), 128, SMEM_BYTES>>>(
        a2, b2, out, 512, 1.0f / (BSCALE * CSCALE));
}

// round 14
// speedup vs baseline: 3.0178x; 1.0903x over previous
#include <cuda_runtime.h>
#include <cuda_fp16.h>
#include <cstdint>

// ----------------------------------------------------------------------------
// MultiHeadAttn, pure fp16 tensor-core pipeline (K=512):
//   1) convert_x : x[8192,512] -> A1 fp16 [8192,512]
//   2) repack_b  : Wq,Wv -> B1 fp16 [1024,512]; Wup -> B2 [512,512]  (x 2^13)
//   3) gemm_mma<HALF_OUT> : QVh[8192,1024] fp16 = A1 @ B1^T, escale=2^-13
//   4) band_attn v4: cp.async fp16 tiles (no cvt), per-warp 16x48 window,
//      S=Q@V^T -> mask+exp -> P -> O=P@V (trans ldmatrix) -> C*2^8 fp16
//   5) gemm_mma<fp32> : out[8192,512] = A2 @ B2^T, escale=2^-21
// ----------------------------------------------------------------------------

#define M_ROWS   8192
#define N_SEQ    4096
#define NHEAD    8
#define CONTEXT  10
#define KDIM     512
#define NCHUNK   8           // 512 / 64

#define BSCALE   8192.0f     // 2^13
#define CSCALE   256.0f      // 2^8

__device__ __half g_A1[M_ROWS * KDIM];
__device__ __half g_A2[M_ROWS * KDIM];
__device__ __half g_B1[1024 * KDIM];
__device__ __half g_B2[512  * KDIM];
__device__ __half g_QVh[M_ROWS * 1024];

// ============================ PTX helpers ====================================
__device__ __forceinline__ uint32_t smem_u32(const void* p) {
    uint32_t a;
    asm("{ .reg .u64 t; cvta.to.shared.u64 t, %1; cvt.u32.u64 %0, t; }"
        : "=r"(a) : "l"(p));
    return a;
}
__device__ __forceinline__ void cp_async16(uint32_t dst, const void* src) {
    asm volatile("cp.async.cg.shared.global [%0], [%1], 16;"
                 :: "r"(dst), "l"(src) : "memory");
}
__device__ __forceinline__ void cp_async16_p(uint32_t dst, const void* src,
                                             uint32_t srcsz) {
    asm volatile("cp.async.cg.shared.global [%0], [%1], 16, %2;"
                 :: "r"(dst), "l"(src), "r"(srcsz) : "memory");
}
__device__ __forceinline__ void cp_commit() {
    asm volatile("cp.async.commit_group;" ::: "memory");
}
template <int N>
__device__ __forceinline__ void cp_wait() {
    asm volatile("cp.async.wait_group %0;" :: "n"(N) : "memory");
}
__device__ __forceinline__ void ldm_x4(uint32_t& r0, uint32_t& r1,
                                       uint32_t& r2, uint32_t& r3, uint32_t a) {
    asm volatile("ldmatrix.sync.aligned.m8n8.x4.shared.b16 {%0,%1,%2,%3}, [%4];"
                 : "=r"(r0), "=r"(r1), "=r"(r2), "=r"(r3) : "r"(a));
}
__device__ __forceinline__ void ldm_x4_t(uint32_t& r0, uint32_t& r1,
                                         uint32_t& r2, uint32_t& r3, uint32_t a) {
    asm volatile("ldmatrix.sync.aligned.m8n8.x4.trans.shared.b16 {%0,%1,%2,%3}, [%4];"
                 : "=r"(r0), "=r"(r1), "=r"(r2), "=r"(r3) : "r"(a));
}
__device__ __forceinline__ void mma16816(float* c, const uint32_t* a,
                                         const uint32_t* b) {
    asm volatile(
        "mma.sync.aligned.m16n8k16.row.col.f32.f16.f16.f32 "
        "{%0,%1,%2,%3}, {%4,%5,%6,%7}, {%8,%9}, {%0,%1,%2,%3};"
        : "+f"(c[0]), "+f"(c[1]), "+f"(c[2]), "+f"(c[3])
        : "r"(a[0]), "r"(a[1]), "r"(a[2]), "r"(a[3]), "r"(b[0]), "r"(b[1]));
}
__device__ __forceinline__ uint32_t h2u(__half2 v) {
    return *reinterpret_cast<uint32_t*>(&v);
}

// ======================= conversion / repack kernels =========================
__global__ void convert_x(const float* __restrict__ x,
                          __half* __restrict__ A1) {
    int idx = blockIdx.x * 256 + threadIdx.x;       // [0, 8192*64)
    int row = idx >> 6;
    int kq  = (idx & 63) * 8;
    const float* src = x + (size_t)row * 512 + kq;
    float4 v0 = *(const float4*)src;
    float4 v1 = *(const float4*)(src + 4);
    __half2 h0 = __floats2half2_rn(v0.x, v0.y);
    __half2 h1 = __floats2half2_rn(v0.z, v0.w);
    __half2 h2 = __floats2half2_rn(v1.x, v1.y);
    __half2 h3 = __floats2half2_rn(v1.z, v1.w);
    *(uint4*)(A1 + (size_t)row * KDIM + kq) =
        make_uint4(h2u(h0), h2u(h1), h2u(h2), h2u(h3));
}

__global__ void repack_b(const float* __restrict__ Wq,
                         const float* __restrict__ Wv,
                         const float* __restrict__ Wup,
                         __half* __restrict__ B1,
                         __half* __restrict__ B2) {
    int idx = blockIdx.x * 256 + threadIdx.x;       // [0, 1024*512 + 512*512)
    if (idx < 1024 * 512) {
        int n = idx >> 9, d = idx & 511;
        float w;
        if (n < 512) {
            int hh = n >> 6, k2 = n & 63;
            w = Wq[hh * (512 * 64) + d * 64 + k2];
        } else {
            int nn = n - 512, hh = nn >> 6, k2 = nn & 63;
            w = Wv[hh * (512 * 64) + d * 64 + k2];
        }
        B1[n * KDIM + d] = __float2half_rn(w * BSCALE);
    } else {
        int i2 = idx - 1024 * 512;
        int n = i2 >> 9, d = i2 & 511;
        B2[n * KDIM + d] = __float2half_rn(Wup[d * 512 + n] * BSCALE);
    }
}

// ====================== HMMA fp16 GEMM (K=512) ===============================
__device__ __forceinline__ void load_tiles(uint32_t sA, uint32_t sB,
                                           const __half* __restrict__ A,
                                           const __half* __restrict__ B,
                                           int bm, int bn, int ck, int tid) {
    const __half* Ab = A + (size_t)bm * KDIM + ck * 64;
    const __half* Bb = B + (size_t)bn * KDIM + ck * 64;
    #pragma unroll
    for (int g = 0; g < 8; g++) {
        int id  = g * 128 + tid;
        int row = id >> 3;
        int c16 = id & 7;
        uint32_t sw = row * 128 + ((c16 * 16) ^ ((row & 7) * 16));
        cp_async16(sA + sw, Ab + (size_t)row * KDIM + c16 * 8);
        cp_async16(sB + sw, Bb + (size_t)row * KDIM + c16 * 8);
    }
}

template <bool HALF_OUT>
__global__ __launch_bounds__(128)
void gemm_mma(const __half* __restrict__ A,
              const __half* __restrict__ B,
              void* __restrict__ Cv, int N, float escale) {
    extern __shared__ char smem[];
    uint32_t sb = smem_u32(smem);
    uint32_t SA[3] = {sb, sb + 32768, sb + 65536};
    uint32_t SB[3] = {sb + 16384, sb + 49152, sb + 81920};

    const int tid  = threadIdx.x;
    const int lane = tid & 31;
    const int warp = tid >> 5;
    const int wm   = (warp >> 1) * 64;
    const int wn   = (warp & 1) * 64;
    const int bm   = blockIdx.y * 128, bn = blockIdx.x * 128;

    const int fr = (lane & 7) + ((lane >> 3) & 1) * 8;
    const int fk = (lane >> 4) * 16;

    float acc[4][8][4];
    #pragma unroll
    for (int i = 0; i < 4; i++)
        #pragma unroll
        for (int j = 0; j < 8; j++)
            #pragma unroll
            for (int q = 0; q < 4; q++) acc[i][j][q] = 0.f;

    load_tiles(SA[0], SB[0], A, B, bm, bn, 0, tid); cp_commit();
    load_tiles(SA[1], SB[1], A, B, bm, bn, 1, tid); cp_commit();

    #pragma unroll 1
    for (int c = 0; c < NCHUNK; c++) {
        const int s = c % 3;
        uint32_t sA = SA[s], sBt = SB[s];

        if (c == NCHUNK - 1) cp_wait<0>(); else cp_wait<1>();
        __syncthreads();

        if (c + 2 < NCHUNK) {
            const int s2 = (c + 2) % 3;
            load_tiles(SA[s2], SB[s2], A, B, bm, bn, c + 2, tid);
            cp_commit();
        }

        #pragma unroll
        for (int ks = 0; ks < 4; ks++) {
            const int k0b = ks * 32;
            uint32_t af[4][4], bf[8][2];
            #pragma unroll
            for (int mi = 0; mi < 4; mi++) {
                int r = wm + mi * 16 + fr;
                uint32_t addr = sA + r * 128 + ((k0b + fk) ^ ((r & 7) * 16));
                ldm_x4(af[mi][0], af[mi][1], af[mi][2], af[mi][3], addr);
            }
            #pragma unroll
            for (int ni = 0; ni < 4; ni++) {
                int r = wn + ni * 16 + fr;
                uint32_t addr = sBt + r * 128 + ((k0b + fk) ^ ((r & 7) * 16));
                uint32_t r0, r1, r2, r3;
                ldm_x4(r0, r1, r2, r3, addr);
                bf[2 * ni][0]     = r0; bf[2 * ni][1]     = r2;
                bf[2 * ni + 1][0] = r1; bf[2 * ni + 1][1] = r3;
            }
            #pragma unroll
            for (int mi = 0; mi < 4; mi++)
                #pragma unroll
                for (int nj = 0; nj < 8; nj++)
                    mma16816(acc[mi][nj], af[mi], bf[nj]);
        }
    }

    const int er = lane >> 2;
    const int ec = (lane & 3) * 2;
    #pragma unroll
    for (int mi = 0; mi < 4; mi++) {
        #pragma unroll
        for (int nj = 0; nj < 8; nj++) {
            int row = bm + wm + mi * 16 + er;
            int col = bn + wn + nj * 8 + ec;
            if (HALF_OUT) {
                __half* Ch = (__half*)Cv;
                __half2 h0 = __floats2half2_rn(acc[mi][nj][0] * escale,
                                               acc[mi][nj][1] * escale);
                __half2 h1 = __floats2half2_rn(acc[mi][nj][2] * escale,
                                               acc[mi][nj][3] * escale);
                *(__half2*)(Ch + (size_t)row * N + col)       = h0;
                *(__half2*)(Ch + (size_t)(row + 8) * N + col) = h1;
            } else {
                float* C = (float*)Cv;
                *(float2*)(C + (size_t)row * N + col) =
                    make_float2(acc[mi][nj][0] * escale, acc[mi][nj][1] * escale);
                *(float2*)(C + (size_t)(row + 8) * N + col) =
                    make_float2(acc[mi][nj][2] * escale, acc[mi][nj][3] * escale);
            }
        }
    }
}

// ========================= band attention v4 (MMA) ===========================
// Block = (b, h, 128-row tile), 256 threads / 8 warps; warp rt owns rows
// [16rt, 16rt+16) whose band cols fall in window [16rt, 16rt+48).
// QVh is fp16: Q/V tiles fill via swizzled cp.async (halo rows zero-filled
// with the src-size=0 form). Stage 1: S[16x48] = Q @ V^T (K=64). Stage 2:
// O[16x64] = P @ V (K=48, B via ldmatrix.x4.trans on row-major V tile).
#define TILE4   128
#define RB4     160
#define PP4     56          // P pitch in halves (112B rows)
#define SM_Q    0
#define SM_V    16384
#define SM_P    36864
#define SM_TOT  51200       // 16K Q + 20K V + 14K P

__global__ __launch_bounds__(256)
void band_attn_kernel(const __half* __restrict__ QVh,
                      __half* __restrict__ A2) {
    extern __shared__ char bsm[];
    const uint32_t sQ = smem_u32(bsm);
    const uint32_t sV = sQ + SM_V;
    const uint32_t sP = sQ + SM_P;
    __half* Ph = (__half*)(bsm + SM_P);

    const int bx   = blockIdx.x;          // [0, 512)
    const int tile = bx & 31;
    const int hd   = (bx >> 5) & 7;
    const int b    = bx >> 8;
    const int i0   = tile * TILE4;
    const int tid  = threadIdx.x;
    const int lane = tid & 31;
    const int rt   = tid >> 5;            // warp = row tile 0..7

    // ---- fill Q tile: swizzled cp.async straight from fp16 QVh ----
    for (int g = tid; g < TILE4 * 8; g += 256) {
        int r = g >> 3, c16 = g & 7;
        uint32_t sw = r * 128 + ((c16 * 16) ^ ((r & 7) * 16));
        cp_async16(sQ + sw,
                   QVh + (size_t)(b * N_SEQ + i0 + r) * 1024 + hd * 64 + c16 * 8);
    }
    // ---- fill V band rows (zero-fill halo via src-size=0) ----
    for (int g = tid; g < RB4 * 8; g += 256) {
        int r = g >> 3, c16 = g & 7;
        int j = i0 - CONTEXT + r;
        bool ok = (j >= 0) && (j < N_SEQ);
        const __half* src = QVh + (size_t)(b * N_SEQ + (ok ? j : 0)) * 1024
                                + 512 + hd * 64 + c16 * 8;
        uint32_t sw = r * 128 + ((c16 * 16) ^ ((r & 7) * 16));
        cp_async16_p(sV + sw, src, ok ? 16u : 0u);
    }
    cp_commit();
    cp_wait<0>();
    __syncthreads();

    const int fr = (lane & 7) + ((lane >> 3) & 1) * 8;
    const int fk = (lane >> 4) * 16;
    const int er = lane >> 2;
    const int ec = (lane & 3) * 2;
    const int rb = rt * 16;               // row/window base

    // ---- stage 1: S[16x48] = Q @ V^T over window ----
    float sacc[6][4];
    #pragma unroll
    for (int t = 0; t < 6; t++)
        #pragma unroll
        for (int q = 0; q < 4; q++) sacc[t][q] = 0.f;

    #pragma unroll
    for (int ks = 0; ks < 4; ks++) {
        const int k0b = ks * 32;
        uint32_t af[4], bf[6][2];
        int ar = rb + fr;
        ldm_x4(af[0], af[1], af[2], af[3],
               sQ + ar * 128 + ((k0b + fk) ^ ((ar & 7) * 16)));
        #pragma unroll
        for (int g = 0; g < 3; g++) {
            int vr = rb + g * 16 + fr;
            uint32_t r0, r1, r2, r3;
            ldm_x4(r0, r1, r2, r3,
                   sV + vr * 128 + ((k0b + fk) ^ ((vr & 7) * 16)));
            bf[2 * g][0]     = r0; bf[2 * g][1]     = r2;
            bf[2 * g + 1][0] = r1; bf[2 * g + 1][1] = r3;
        }
        #pragma unroll
        for (int t = 0; t < 6; t++)
            mma16816(sacc[t], af, bf[t]);
    }

    // ---- mask + exp -> P (local cols), rowsums in registers ----
    const float sscale = 1.0f / 16.0f;
    float slo = 0.f, shi = 0.f;
    #pragma unroll
    for (int t = 0; t < 6; t++) {
        int lc = t * 8 + ec;                    // local window col
        #pragma unroll
        for (int half = 0; half < 2; half++) {
            int rl = er + half * 8;             // row within warp tile
            float e0 = 0.f, e1 = 0.f;
            int d0 = lc - rl, d1 = d0 + 1;
            int j0 = i0 - CONTEXT + rb + lc;
            if (d0 >= 0 && d0 <= 2 * CONTEXT && d0 != CONTEXT &&
                j0 >= 0 && j0 < N_SEQ)
                e0 = __expf(sacc[t][2 * half] * sscale);
            if (d1 >= 0 && d1 <= 2 * CONTEXT && d1 != CONTEXT &&
                j0 + 1 >= 0 && j0 + 1 < N_SEQ)
                e1 = __expf(sacc[t][2 * half + 1] * sscale);
            *(__half2*)&Ph[(rb + rl) * PP4 + lc] = __floats2half2_rn(e0, e1);
            if (half == 0) slo += e0 + e1; else shi += e0 + e1;
        }
    }
    slo += __shfl_xor_sync(0xffffffffu, slo, 1);
    slo += __shfl_xor_sync(0xffffffffu, slo, 2);
    shi += __shfl_xor_sync(0xffffffffu, shi, 1);
    shi += __shfl_xor_sync(0xffffffffu, shi, 2);
    __syncwarp();          // this warp's P rows visible to its own ldmatrix

    // ---- stage 2: O[16x64] = P @ V (K = 48, B via trans ldmatrix) ----
    float oacc[8][4];
    #pragma unroll
    for (int t = 0; t < 8; t++)
        #pragma unroll
        for (int q = 0; q < 4; q++) oacc[t][q] = 0.f;

    #pragma unroll
    for (int ks = 0; ks < 3; ks++) {
        uint32_t af[4], bf[8][2];
        int ar = rb + fr;
        ldm_x4(af[0], af[1], af[2], af[3], sP + ar * 112 + ks * 32 + fk);
        #pragma unroll
        for (int g = 0; g < 4; g++) {
            int vr = rb + ks * 16 + fr;          // k index (band row)
            uint32_t nb = g * 32 + fk;           // n (dim) byte offset
            uint32_t r0, r1, r2, r3;
            ldm_x4_t(r0, r1, r2, r3,
                     sV + vr * 128 + (nb ^ ((vr & 7) * 16)));
            bf[2 * g][0]     = r0; bf[2 * g][1]     = r1;
            bf[2 * g + 1][0] = r2; bf[2 * g + 1][1] = r3;
        }
        #pragma unroll
        for (int t = 0; t < 8; t++)
            mma16816(oacc[t], af, bf[t]);
    }

    // ---- normalize + store C*2^8 as fp16 ----
    float inv0 = CSCALE / slo;
    float inv1 = CSCALE / shi;
    int il0 = i0 + rb + er, il1 = il0 + 8;
    #pragma unroll
    for (int t = 0; t < 8; t++) {
        int d = t * 8 + ec;
        __half2 h0 = __floats2half2_rn(oacc[t][0] * inv0, oacc[t][1] * inv0);
        __half2 h1 = __floats2half2_rn(oacc[t][2] * inv1, oacc[t][3] * inv1);
        *(__half2*)(A2 + (size_t)(b * N_SEQ + il0) * KDIM + hd * 64 + d) = h0;
        *(__half2*)(A2 + (size_t)(b * N_SEQ + il1) * KDIM + hd * 64 + d) = h1;
    }
}

// ================================ launch =====================================
extern "C" void kernel_launch(void* const* d_in, const int* in_sizes, int n_in,
                              void* d_out, int out_size) {
    const float* x   = (const float*)d_in[0];
    const float* Wq  = (const float*)d_in[1];
    const float* Wv  = (const float*)d_in[2];
    const float* Wup = (const float*)d_in[3];

    __half *a1, *a2, *b1, *b2, *qvh;
    cudaGetSymbolAddress((void**)&a1,  g_A1);
    cudaGetSymbolAddress((void**)&a2,  g_A2);
    cudaGetSymbolAddress((void**)&b1,  g_B1);
    cudaGetSymbolAddress((void**)&b2,  g_B2);
    cudaGetSymbolAddress((void**)&qvh, g_QVh);

    const int SMEM_BYTES = 98304;   // 3 stages x 32KB (gemm)
    cudaFuncSetAttribute(gemm_mma<true>,
                         cudaFuncAttributeMaxDynamicSharedMemorySize, SMEM_BYTES);
    cudaFuncSetAttribute(gemm_mma<false>,
                         cudaFuncAttributeMaxDynamicSharedMemorySize, SMEM_BYTES);
    cudaFuncSetAttribute(band_attn_kernel,
                         cudaFuncAttributeMaxDynamicSharedMemorySize, SM_TOT);

    convert_x<<<(M_ROWS * 64) / 256, 256>>>(x, a1);
    repack_b<<<(1024 * 512 + 512 * 512) / 256, 256>>>(Wq, Wv, Wup, b1, b2);

    gemm_mma<true><<<dim3(1024 / 128, M_ROWS / 128), 128, SMEM_BYTES>>>(
        a1, b1, qvh, 1024, 1.0f / BSCALE);
    band_attn_kernel<<<2 * NHEAD * (N_SEQ / TILE4), 256, SM_TOT>>>(qvh, a2);
    gemm_mma<false><<<dim3(512 / 128, M_ROWS / 128), 128, SMEM_BYTES>>>(
        a2, b2, d_out, 512, 1.0f / (BSCALE * CSCALE));
}

// round 15
// speedup vs baseline: 3.1351x; 1.0389x over previous
#include <cuda_runtime.h>
#include <cuda_fp16.h>
#include <cstdint>

// ----------------------------------------------------------------------------
// MultiHeadAttn, pure fp16 tensor-core pipeline (K=512):
//   1) prep_kernel : x -> A1 fp16 [8192,512]; Wq,Wv -> B1 [1024,512],
//                    Wup^T -> B2 [512,512] (x 2^13)  (single launch)
//   2) gemm_mma<HALF_OUT> : QVh[8192,1024] fp16 = A1 @ B1^T, escale=2^-13
//   3) band_attn v5: cp.async fp16 tiles, per-warp 16x48 window,
//      S=Q@V^T -> mask+exp -> P -> O=P@V (trans ldmatrix) -> smem-staged
//      coalesced A2 stores (C*2^8 fp16)
//   4) gemm_mma<fp32> : out[8192,512] = A2 @ B2^T, escale=2^-21
// ----------------------------------------------------------------------------

#define M_ROWS   8192
#define N_SEQ    4096
#define NHEAD    8
#define CONTEXT  10
#define KDIM     512
#define NCHUNK   8           // 512 / 64

#define BSCALE   8192.0f     // 2^13
#define CSCALE   256.0f      // 2^8

__device__ __half g_A1[M_ROWS * KDIM];
__device__ __half g_A2[M_ROWS * KDIM];
__device__ __half g_B1[1024 * KDIM];
__device__ __half g_B2[512  * KDIM];
__device__ __half g_QVh[M_ROWS * 1024];

// ============================ PTX helpers ====================================
__device__ __forceinline__ uint32_t smem_u32(const void* p) {
    uint32_t a;
    asm("{ .reg .u64 t; cvta.to.shared.u64 t, %1; cvt.u32.u64 %0, t; }"
        : "=r"(a) : "l"(p));
    return a;
}
__device__ __forceinline__ void cp_async16(uint32_t dst, const void* src) {
    asm volatile("cp.async.cg.shared.global [%0], [%1], 16;"
                 :: "r"(dst), "l"(src) : "memory");
}
__device__ __forceinline__ void cp_async16_p(uint32_t dst, const void* src,
                                             uint32_t srcsz) {
    asm volatile("cp.async.cg.shared.global [%0], [%1], 16, %2;"
                 :: "r"(dst), "l"(src), "r"(srcsz) : "memory");
}
__device__ __forceinline__ void cp_commit() {
    asm volatile("cp.async.commit_group;" ::: "memory");
}
template <int N>
__device__ __forceinline__ void cp_wait() {
    asm volatile("cp.async.wait_group %0;" :: "n"(N) : "memory");
}
__device__ __forceinline__ void ldm_x4(uint32_t& r0, uint32_t& r1,
                                       uint32_t& r2, uint32_t& r3, uint32_t a) {
    asm volatile("ldmatrix.sync.aligned.m8n8.x4.shared.b16 {%0,%1,%2,%3}, [%4];"
                 : "=r"(r0), "=r"(r1), "=r"(r2), "=r"(r3) : "r"(a));
}
__device__ __forceinline__ void ldm_x4_t(uint32_t& r0, uint32_t& r1,
                                         uint32_t& r2, uint32_t& r3, uint32_t a) {
    asm volatile("ldmatrix.sync.aligned.m8n8.x4.trans.shared.b16 {%0,%1,%2,%3}, [%4];"
                 : "=r"(r0), "=r"(r1), "=r"(r2), "=r"(r3) : "r"(a));
}
__device__ __forceinline__ void mma16816(float* c, const uint32_t* a,
                                         const uint32_t* b) {
    asm volatile(
        "mma.sync.aligned.m16n8k16.row.col.f32.f16.f16.f32 "
        "{%0,%1,%2,%3}, {%4,%5,%6,%7}, {%8,%9}, {%0,%1,%2,%3};"
        : "+f"(c[0]), "+f"(c[1]), "+f"(c[2]), "+f"(c[3])
        : "r"(a[0]), "r"(a[1]), "r"(a[2]), "r"(a[3]), "r"(b[0]), "r"(b[1]));
}
__device__ __forceinline__ uint32_t h2u(__half2 v) {
    return *reinterpret_cast<uint32_t*>(&v);
}

// ===================== fused conversion / repack kernel ======================
// blocks [0, 2048)            : x -> A1 fp16 (8 elems/thread)
// blocks [2048, 2048+3072)    : B1 from Wq/Wv, B2 from Wup^T (x 2^13)
__global__ void prep_kernel(const float* __restrict__ x,
                            const float* __restrict__ Wq,
                            const float* __restrict__ Wv,
                            const float* __restrict__ Wup,
                            __half* __restrict__ A1,
                            __half* __restrict__ B1,
                            __half* __restrict__ B2) {
    int bid = blockIdx.x;
    if (bid < 2048) {
        int idx = bid * 256 + threadIdx.x;          // [0, 8192*64)
        int row = idx >> 6;
        int kq  = (idx & 63) * 8;
        const float* src = x + (size_t)row * 512 + kq;
        float4 v0 = *(const float4*)src;
        float4 v1 = *(const float4*)(src + 4);
        __half2 h0 = __floats2half2_rn(v0.x, v0.y);
        __half2 h1 = __floats2half2_rn(v0.z, v0.w);
        __half2 h2 = __floats2half2_rn(v1.x, v1.y);
        __half2 h3 = __floats2half2_rn(v1.z, v1.w);
        *(uint4*)(A1 + (size_t)row * KDIM + kq) =
            make_uint4(h2u(h0), h2u(h1), h2u(h2), h2u(h3));
    } else {
        int idx = (bid - 2048) * 256 + threadIdx.x; // [0, 1024*512 + 512*512)
        if (idx < 1024 * 512) {
            int n = idx >> 9, d = idx & 511;
            float w;
            if (n < 512) {
                int hh = n >> 6, k2 = n & 63;
                w = Wq[hh * (512 * 64) + d * 64 + k2];
            } else {
                int nn = n - 512, hh = nn >> 6, k2 = nn & 63;
                w = Wv[hh * (512 * 64) + d * 64 + k2];
            }
            B1[n * KDIM + d] = __float2half_rn(w * BSCALE);
        } else {
            int i2 = idx - 1024 * 512;
            int n = i2 >> 9, d = i2 & 511;
            B2[n * KDIM + d] = __float2half_rn(Wup[d * 512 + n] * BSCALE);
        }
    }
}

// ====================== HMMA fp16 GEMM (K=512) ===============================
__device__ __forceinline__ void load_tiles(uint32_t sA, uint32_t sB,
                                           const __half* __restrict__ A,
                                           const __half* __restrict__ B,
                                           int bm, int bn, int ck, int tid) {
    const __half* Ab = A + (size_t)bm * KDIM + ck * 64;
    const __half* Bb = B + (size_t)bn * KDIM + ck * 64;
    #pragma unroll
    for (int g = 0; g < 8; g++) {
        int id  = g * 128 + tid;
        int row = id >> 3;
        int c16 = id & 7;
        uint32_t sw = row * 128 + ((c16 * 16) ^ ((row & 7) * 16));
        cp_async16(sA + sw, Ab + (size_t)row * KDIM + c16 * 8);
        cp_async16(sB + sw, Bb + (size_t)row * KDIM + c16 * 8);
    }
}

template <bool HALF_OUT>
__global__ __launch_bounds__(128)
void gemm_mma(const __half* __restrict__ A,
              const __half* __restrict__ B,
              void* __restrict__ Cv, int N, float escale) {
    extern __shared__ char smem[];
    uint32_t sb = smem_u32(smem);
    uint32_t SA[3] = {sb, sb + 32768, sb + 65536};
    uint32_t SB[3] = {sb + 16384, sb + 49152, sb + 81920};

    const int tid  = threadIdx.x;
    const int lane = tid & 31;
    const int warp = tid >> 5;
    const int wm   = (warp >> 1) * 64;
    const int wn   = (warp & 1) * 64;
    const int bm   = blockIdx.y * 128, bn = blockIdx.x * 128;

    const int fr = (lane & 7) + ((lane >> 3) & 1) * 8;
    const int fk = (lane >> 4) * 16;

    float acc[4][8][4];
    #pragma unroll
    for (int i = 0; i < 4; i++)
        #pragma unroll
        for (int j = 0; j < 8; j++)
            #pragma unroll
            for (int q = 0; q < 4; q++) acc[i][j][q] = 0.f;

    load_tiles(SA[0], SB[0], A, B, bm, bn, 0, tid); cp_commit();
    load_tiles(SA[1], SB[1], A, B, bm, bn, 1, tid); cp_commit();

    #pragma unroll 1
    for (int c = 0; c < NCHUNK; c++) {
        const int s = c % 3;
        uint32_t sA = SA[s], sBt = SB[s];

        if (c == NCHUNK - 1) cp_wait<0>(); else cp_wait<1>();
        __syncthreads();

        if (c + 2 < NCHUNK) {
            const int s2 = (c + 2) % 3;
            load_tiles(SA[s2], SB[s2], A, B, bm, bn, c + 2, tid);
            cp_commit();
        }

        #pragma unroll
        for (int ks = 0; ks < 4; ks++) {
            const int k0b = ks * 32;
            uint32_t af[4][4], bf[8][2];
            #pragma unroll
            for (int mi = 0; mi < 4; mi++) {
                int r = wm + mi * 16 + fr;
                uint32_t addr = sA + r * 128 + ((k0b + fk) ^ ((r & 7) * 16));
                ldm_x4(af[mi][0], af[mi][1], af[mi][2], af[mi][3], addr);
            }
            #pragma unroll
            for (int ni = 0; ni < 4; ni++) {
                int r = wn + ni * 16 + fr;
                uint32_t addr = sBt + r * 128 + ((k0b + fk) ^ ((r & 7) * 16));
                uint32_t r0, r1, r2, r3;
                ldm_x4(r0, r1, r2, r3, addr);
                bf[2 * ni][0]     = r0; bf[2 * ni][1]     = r2;
                bf[2 * ni + 1][0] = r1; bf[2 * ni + 1][1] = r3;
            }
            #pragma unroll
            for (int mi = 0; mi < 4; mi++)
                #pragma unroll
                for (int nj = 0; nj < 8; nj++)
                    mma16816(acc[mi][nj], af[mi], bf[nj]);
        }
    }

    const int er = lane >> 2;
    const int ec = (lane & 3) * 2;
    #pragma unroll
    for (int mi = 0; mi < 4; mi++) {
        #pragma unroll
        for (int nj = 0; nj < 8; nj++) {
            int row = bm + wm + mi * 16 + er;
            int col = bn + wn + nj * 8 + ec;
            if (HALF_OUT) {
                __half* Ch = (__half*)Cv;
                __half2 h0 = __floats2half2_rn(acc[mi][nj][0] * escale,
                                               acc[mi][nj][1] * escale);
                __half2 h1 = __floats2half2_rn(acc[mi][nj][2] * escale,
                                               acc[mi][nj][3] * escale);
                *(__half2*)(Ch + (size_t)row * N + col)       = h0;
                *(__half2*)(Ch + (size_t)(row + 8) * N + col) = h1;
            } else {
                float* C = (float*)Cv;
                *(float2*)(C + (size_t)row * N + col) =
                    make_float2(acc[mi][nj][0] * escale, acc[mi][nj][1] * escale);
                *(float2*)(C + (size_t)(row + 8) * N + col) =
                    make_float2(acc[mi][nj][2] * escale, acc[mi][nj][3] * escale);
            }
        }
    }
}

// ========================= band attention v5 (MMA) ===========================
// Block = (b, h, 128-row tile), 256 threads / 8 warps; warp rt owns rows
// [16rt, 16rt+16), band cols in window [16rt, 16rt+48).
// Fill: swizzled cp.async from fp16 QVh (halo rows zero-filled, src-size=0).
// Stage 1: S[16x48] = Q @ V^T (K=64) -> mask+exp -> P (fp16, local cols).
// Stage 2: O[16x64] = P @ V (K=48, B via ldmatrix.x4.trans).
// Epilogue: O staged (swizzled) into the spent Q region, then cooperative
// STG.128 of full 128B head-rows (coalesced).
#define TILE4   128
#define RB4     160
#define PP4     56          // P pitch in halves (112B rows)
#define SM_Q    0
#define SM_V    16384
#define SM_P    36864
#define SM_TOT  51200       // 16K Q/O + 20K V + 14K P

__global__ __launch_bounds__(256)
void band_attn_kernel(const __half* __restrict__ QVh,
                      __half* __restrict__ A2) {
    extern __shared__ char bsm[];
    const uint32_t sQ = smem_u32(bsm);
    const uint32_t sV = sQ + SM_V;
    const uint32_t sP = sQ + SM_P;
    __half* Ph = (__half*)(bsm + SM_P);

    const int bx   = blockIdx.x;          // [0, 512)
    const int tile = bx & 31;
    const int hd   = (bx >> 5) & 7;
    const int b    = bx >> 8;
    const int i0   = tile * TILE4;
    const int tid  = threadIdx.x;
    const int lane = tid & 31;
    const int rt   = tid >> 5;            // warp = row tile 0..7

    // ---- fill Q tile: swizzled cp.async straight from fp16 QVh ----
    for (int g = tid; g < TILE4 * 8; g += 256) {
        int r = g >> 3, c16 = g & 7;
        uint32_t sw = r * 128 + ((c16 * 16) ^ ((r & 7) * 16));
        cp_async16(sQ + sw,
                   QVh + (size_t)(b * N_SEQ + i0 + r) * 1024 + hd * 64 + c16 * 8);
    }
    // ---- fill V band rows (zero-fill halo via src-size=0) ----
    for (int g = tid; g < RB4 * 8; g += 256) {
        int r = g >> 3, c16 = g & 7;
        int j = i0 - CONTEXT + r;
        bool ok = (j >= 0) && (j < N_SEQ);
        const __half* src = QVh + (size_t)(b * N_SEQ + (ok ? j : 0)) * 1024
                                + 512 + hd * 64 + c16 * 8;
        uint32_t sw = r * 128 + ((c16 * 16) ^ ((r & 7) * 16));
        cp_async16_p(sV + sw, src, ok ? 16u : 0u);
    }
    cp_commit();
    cp_wait<0>();
    __syncthreads();

    const int fr = (lane & 7) + ((lane >> 3) & 1) * 8;
    const int fk = (lane >> 4) * 16;
    const int er = lane >> 2;
    const int ec = (lane & 3) * 2;
    const int rb = rt * 16;               // row/window base

    // ---- stage 1: S[16x48] = Q @ V^T over window ----
    float sacc[6][4];
    #pragma unroll
    for (int t = 0; t < 6; t++)
        #pragma unroll
        for (int q = 0; q < 4; q++) sacc[t][q] = 0.f;

    #pragma unroll
    for (int ks = 0; ks < 4; ks++) {
        const int k0b = ks * 32;
        uint32_t af[4], bf[6][2];
        int ar = rb + fr;
        ldm_x4(af[0], af[1], af[2], af[3],
               sQ + ar * 128 + ((k0b + fk) ^ ((ar & 7) * 16)));
        #pragma unroll
        for (int g = 0; g < 3; g++) {
            int vr = rb + g * 16 + fr;
            uint32_t r0, r1, r2, r3;
            ldm_x4(r0, r1, r2, r3,
                   sV + vr * 128 + ((k0b + fk) ^ ((vr & 7) * 16)));
            bf[2 * g][0]     = r0; bf[2 * g][1]     = r2;
            bf[2 * g + 1][0] = r1; bf[2 * g + 1][1] = r3;
        }
        #pragma unroll
        for (int t = 0; t < 6; t++)
            mma16816(sacc[t], af, bf[t]);
    }

    // ---- mask + exp -> P (local cols), rowsums in registers ----
    const float sscale = 1.0f / 16.0f;
    float slo = 0.f, shi = 0.f;
    #pragma unroll
    for (int t = 0; t < 6; t++) {
        int lc = t * 8 + ec;                    // local window col
        #pragma unroll
        for (int half = 0; half < 2; half++) {
            int rl = er + half * 8;             // row within warp tile
            float e0 = 0.f, e1 = 0.f;
            int d0 = lc - rl, d1 = d0 + 1;
            int j0 = i0 - CONTEXT + rb + lc;
            if (d0 >= 0 && d0 <= 2 * CONTEXT && d0 != CONTEXT &&
                j0 >= 0 && j0 < N_SEQ)
                e0 = __expf(sacc[t][2 * half] * sscale);
            if (d1 >= 0 && d1 <= 2 * CONTEXT && d1 != CONTEXT &&
                j0 + 1 >= 0 && j0 + 1 < N_SEQ)
                e1 = __expf(sacc[t][2 * half + 1] * sscale);
            *(__half2*)&Ph[(rb + rl) * PP4 + lc] = __floats2half2_rn(e0, e1);
            if (half == 0) slo += e0 + e1; else shi += e0 + e1;
        }
    }
    slo += __shfl_xor_sync(0xffffffffu, slo, 1);
    slo += __shfl_xor_sync(0xffffffffu, slo, 2);
    shi += __shfl_xor_sync(0xffffffffu, shi, 1);
    shi += __shfl_xor_sync(0xffffffffu, shi, 2);
    __syncwarp();          // this warp's P rows visible to its own ldmatrix

    // ---- stage 2: O[16x64] = P @ V (K = 48, B via trans ldmatrix) ----
    float oacc[8][4];
    #pragma unroll
    for (int t = 0; t < 8; t++)
        #pragma unroll
        for (int q = 0; q < 4; q++) oacc[t][q] = 0.f;

    #pragma unroll
    for (int ks = 0; ks < 3; ks++) {
        uint32_t af[4], bf[8][2];
        int ar = rb + fr;
        ldm_x4(af[0], af[1], af[2], af[3], sP + ar * 112 + ks * 32 + fk);
        #pragma unroll
        for (int g = 0; g < 4; g++) {
            int vr = rb + ks * 16 + fr;          // k index (band row)
            uint32_t nb = g * 32 + fk;           // n (dim) byte offset
            uint32_t r0, r1, r2, r3;
            ldm_x4_t(r0, r1, r2, r3,
                     sV + vr * 128 + (nb ^ ((vr & 7) * 16)));
            bf[2 * g][0]     = r0; bf[2 * g][1]     = r1;
            bf[2 * g + 1][0] = r2; bf[2 * g + 1][1] = r3;
        }
        #pragma unroll
        for (int t = 0; t < 8; t++)
            mma16816(oacc[t], af, bf[t]);
    }

    // ---- normalize, stage O into spent Q region (swizzled), coalesced STG --
    // Q rows [rb, rb+16) were only ever read by this warp (stage-1 A frags),
    // so in-warp program order makes the overwrite safe without a barrier.
    float inv0 = CSCALE / slo;
    float inv1 = CSCALE / shi;
    #pragma unroll
    for (int t = 0; t < 8; t++) {
        __half2 h0 = __floats2half2_rn(oacc[t][0] * inv0, oacc[t][1] * inv0);
        __half2 h1 = __floats2half2_rn(oacc[t][2] * inv1, oacc[t][3] * inv1);
        int r0 = rb + er, r1 = r0 + 8;
        uint32_t a0 = sQ + r0 * 128 + ((t * 16) ^ ((r0 & 7) * 16)) + 4 * (lane & 3);
        uint32_t a1 = sQ + r1 * 128 + ((t * 16) ^ ((r1 & 7) * 16)) + 4 * (lane & 3);
        *(__half2*)(bsm + (a0 - sQ) + SM_Q) = h0;
        *(__half2*)(bsm + (a1 - sQ) + SM_Q) = h1;
    }
    __syncthreads();

    // cooperative coalesced store: 128 rows x 128B (one head-row per STG.128 q)
    for (int g = tid; g < TILE4 * 8; g += 256) {
        int row = g >> 3, q = g & 7;
        uint32_t off = row * 128 + ((q * 16) ^ ((row & 7) * 16));
        uint4 v = *(uint4*)(bsm + SM_Q + off);
        *(uint4*)(A2 + (size_t)(b * N_SEQ + i0 + row) * KDIM + hd * 64 + q * 8) = v;
    }
}

// ================================ launch =====================================
extern "C" void kernel_launch(void* const* d_in, const int* in_sizes, int n_in,
                              void* d_out, int out_size) {
    const float* x   = (const float*)d_in[0];
    const float* Wq  = (const float*)d_in[1];
    const float* Wv  = (const float*)d_in[2];
    const float* Wup = (const float*)d_in[3];

    __half *a1, *a2, *b1, *b2, *qvh;
    cudaGetSymbolAddress((void**)&a1,  g_A1);
    cudaGetSymbolAddress((void**)&a2,  g_A2);
    cudaGetSymbolAddress((void**)&b1,  g_B1);
    cudaGetSymbolAddress((void**)&b2,  g_B2);
    cudaGetSymbolAddress((void**)&qvh, g_QVh);

    const int SMEM_BYTES = 98304;   // 3 stages x 32KB (gemm)
    cudaFuncSetAttribute(gemm_mma<true>,
                         cudaFuncAttributeMaxDynamicSharedMemorySize, SMEM_BYTES);
    cudaFuncSetAttribute(gemm_mma<false>,
                         cudaFuncAttributeMaxDynamicSharedMemorySize, SMEM_BYTES);
    cudaFuncSetAttribute(band_attn_kernel,
                         cudaFuncAttributeMaxDynamicSharedMemorySize, SM_TOT);

    // fused conversions: 2048 blocks for x->A1, 3072 for B1/B2
    prep_kernel<<<2048 + 3072, 256>>>(x, Wq, Wv, Wup, a1, b1, b2);

    gemm_mma<true><<<dim3(1024 / 128, M_ROWS / 128), 128, SMEM_BYTES>>>(
        a1, b1, qvh, 1024, 1.0f / BSCALE);
    band_attn_kernel<<<2 * NHEAD * (N_SEQ / TILE4), 256, SM_TOT>>>(qvh, a2);
    gemm_mma<false><<<dim3(512 / 128, M_ROWS / 128), 128, SMEM_BYTES>>>(
        a2, b2, d_out, 512, 1.0f / (BSCALE * CSCALE));
}